// round 5
// baseline (speedup 1.0000x reference)
#include <cuda_runtime.h>

// ---------------------------------------------------------------------------
// SNN forward: 25 timesteps, 3 LIF-linear layers (1024->2048->2048->1024),
// batch 256. fp32 FFMA GEMM with fused LIF epilogue.
//
// Output layout (flattened tuple from reference):
//   [0, 25*256*1024)              : spike record of last layer, (T,B,1024)
//   [25*256*1024, +256*1024)      : final membrane of last layer, (B,1024)
// ---------------------------------------------------------------------------

constexpr int T_STEPS = 25;
constexpr int BATCH   = 256;
constexpr int F0 = 1024, F1 = 2048, F2 = 2048, F3 = 1024;

// Persistent scratch (no cudaMalloc allowed): membranes + inter-layer spikes.
__device__ float g_m0[BATCH * F1];
__device__ float g_m1[BATCH * F2];
__device__ float g_m2[BATCH * F3];
__device__ float g_s0[BATCH * F1];
__device__ float g_s1[BATCH * F2];

__global__ void zero_mems_kernel() {
    int idx = blockIdx.x * blockDim.x + threadIdx.x;
    int stride = gridDim.x * blockDim.x;
    for (int i = idx; i < BATCH * F1; i += stride) g_m0[i] = 0.0f;
    for (int i = idx; i < BATCH * F2; i += stride) g_m1[i] = 0.0f;
    for (int i = idx; i < BATCH * F3; i += stride) g_m2[i] = 0.0f;
}

__global__ void copy_final_mem_kernel(float* __restrict__ dst) {
    int i = blockIdx.x * blockDim.x + threadIdx.x;
    if (i < BATCH * F3) dst[i] = g_m2[i];
}

// ---------------------------------------------------------------------------
// Fused GEMM + LIF.
//   cur[b,n] = sum_k A[b,k] * W[n,k] + bias[n]       (A: (BATCH,K), W: (N,K))
//   m = 0.9*m + cur ; s = (m > 1) ; m -= s
// Tile: BM=64 x BN x BK=16, 256 threads, TMxTN register micro-tile.
// ---------------------------------------------------------------------------
template <int BN, int TN>
__global__ __launch_bounds__(256)
void lif_gemm_kernel(const float* __restrict__ A,
                     const float* __restrict__ W,
                     const float* __restrict__ bias,
                     float* __restrict__ mem,
                     float* __restrict__ spk,
                     int K, int N)
{
    constexpr int BM = 64, BK = 16, TM = 4, THREADS = 256;
    constexpr int TX = BN / TN;          // threads along n
    constexpr int TY = THREADS / TX;     // threads along m
    static_assert(TY * TM == BM, "tile mismatch");
    constexpr int PAD = 4;               // keeps float4 alignment (stride mult of 4)

    __shared__ float As[BK][BM + PAD];   // k-major (transposed)
    __shared__ float Bs[BK][BN + PAD];

    const int tid = threadIdx.x;
    const int tx = tid % TX;
    const int ty = tid / TX;
    const int bm = blockIdx.y * BM;
    const int bn = blockIdx.x * BN;

    // ---- A tile loader: 64x16 floats, one float4 along k per thread ----
    const int a_row = tid >> 2;          // 0..63
    const int a_kc  = (tid & 3) << 2;    // 0,4,8,12
    const float* a_ptr = A + (size_t)(bm + a_row) * K + a_kc;

    // ---- B tile loader: BNx16 floats ----
    constexpr int B_PER = BN * BK / THREADS;   // 4 (BN=64) or 2 (BN=32)
    int b_row, b_kc;
    if constexpr (B_PER == 4) { b_row = tid >> 2; b_kc = (tid & 3) << 2; }
    else                      { b_row = tid >> 3; b_kc = (tid & 7) << 1; }
    const float* b_ptr = W + (size_t)(bn + b_row) * K + b_kc;

    float acc[TM][TN];
    #pragma unroll
    for (int i = 0; i < TM; i++)
        #pragma unroll
        for (int j = 0; j < TN; j++) acc[i][j] = 0.0f;

    const int ktiles = K / BK;

    // Prefetch tile 0 into registers
    float4 a_reg = *reinterpret_cast<const float4*>(a_ptr);
    float4 b_reg4;
    float2 b_reg2;
    if constexpr (B_PER == 4) b_reg4 = *reinterpret_cast<const float4*>(b_ptr);
    else                      b_reg2 = *reinterpret_cast<const float2*>(b_ptr);

    // Store tile 0 to smem (transposed)
    As[a_kc + 0][a_row] = a_reg.x;
    As[a_kc + 1][a_row] = a_reg.y;
    As[a_kc + 2][a_row] = a_reg.z;
    As[a_kc + 3][a_row] = a_reg.w;
    if constexpr (B_PER == 4) {
        Bs[b_kc + 0][b_row] = b_reg4.x;
        Bs[b_kc + 1][b_row] = b_reg4.y;
        Bs[b_kc + 2][b_row] = b_reg4.z;
        Bs[b_kc + 3][b_row] = b_reg4.w;
    } else {
        Bs[b_kc + 0][b_row] = b_reg2.x;
        Bs[b_kc + 1][b_row] = b_reg2.y;
    }
    __syncthreads();

    for (int kt = 1; kt <= ktiles; ++kt) {
        // Prefetch next tile (hidden under compute below)
        if (kt < ktiles) {
            a_reg = *reinterpret_cast<const float4*>(a_ptr + kt * BK);
            if constexpr (B_PER == 4)
                b_reg4 = *reinterpret_cast<const float4*>(b_ptr + kt * BK);
            else
                b_reg2 = *reinterpret_cast<const float2*>(b_ptr + kt * BK);
        }

        // Compute current tile from smem
        #pragma unroll
        for (int k = 0; k < BK; ++k) {
            float4 av = *reinterpret_cast<const float4*>(&As[k][ty * TM]);
            float a[TM] = {av.x, av.y, av.z, av.w};
            float b[TN];
            if constexpr (TN == 4) {
                float4 bv = *reinterpret_cast<const float4*>(&Bs[k][tx * TN]);
                b[0] = bv.x; b[1] = bv.y; b[2] = bv.z; b[3] = bv.w;
            } else {
                float2 bv = *reinterpret_cast<const float2*>(&Bs[k][tx * TN]);
                b[0] = bv.x; b[1] = bv.y;
            }
            #pragma unroll
            for (int i = 0; i < TM; i++)
                #pragma unroll
                for (int j = 0; j < TN; j++)
                    acc[i][j] += a[i] * b[j];
        }
        __syncthreads();

        if (kt < ktiles) {
            As[a_kc + 0][a_row] = a_reg.x;
            As[a_kc + 1][a_row] = a_reg.y;
            As[a_kc + 2][a_row] = a_reg.z;
            As[a_kc + 3][a_row] = a_reg.w;
            if constexpr (B_PER == 4) {
                Bs[b_kc + 0][b_row] = b_reg4.x;
                Bs[b_kc + 1][b_row] = b_reg4.y;
                Bs[b_kc + 2][b_row] = b_reg4.z;
                Bs[b_kc + 3][b_row] = b_reg4.w;
            } else {
                Bs[b_kc + 0][b_row] = b_reg2.x;
                Bs[b_kc + 1][b_row] = b_reg2.y;
            }
            __syncthreads();
        }
    }

    // ---- Fused LIF epilogue ----
    #pragma unroll
    for (int i = 0; i < TM; i++) {
        const int row = bm + ty * TM + i;
        #pragma unroll
        for (int j = 0; j < TN; j++) {
            const int col = bn + tx * TN + j;
            const size_t idx = (size_t)row * N + col;
            float cur = acc[i][j] + __ldg(&bias[col]);
            float m = 0.9f * mem[idx] + cur;
            float s = (m > 1.0f) ? 1.0f : 0.0f;   // spike(m - 1): sign-exact vs ref
            mem[idx] = m - s;                     // subtract reset (threshold=1)
            spk[idx] = s;
        }
    }
}

extern "C" void kernel_launch(void* const* d_in, const int* in_sizes, int n_in,
                              void* d_out, int out_size)
{
    (void)in_sizes; (void)n_in;
    const float* x  = (const float*)d_in[0];   // (25,256,1024)
    const float* w0 = (const float*)d_in[1];   // (2048,1024)
    const float* b0 = (const float*)d_in[2];   // (2048)
    const float* w1 = (const float*)d_in[3];   // (2048,2048)
    const float* b1 = (const float*)d_in[4];   // (2048)
    const float* w2 = (const float*)d_in[5];   // (1024,2048)
    const float* b2 = (const float*)d_in[6];   // (1024)
    float* out = (float*)d_out;

    float *m0, *m1, *m2, *s0, *s1;
    cudaGetSymbolAddress((void**)&m0, g_m0);
    cudaGetSymbolAddress((void**)&m1, g_m1);
    cudaGetSymbolAddress((void**)&m2, g_m2);
    cudaGetSymbolAddress((void**)&s0, g_s0);
    cudaGetSymbolAddress((void**)&s1, g_s1);

    zero_mems_kernel<<<512, 256>>>();

    const dim3 block(256);
    const dim3 grid_l0(F1 / 64, BATCH / 64);   // 32 x 4 = 128 CTAs
    const dim3 grid_l1(F2 / 64, BATCH / 64);   // 32 x 4 = 128 CTAs
    const dim3 grid_l2(F3 / 32, BATCH / 64);   // 32 x 4 = 128 CTAs

    for (int t = 0; t < T_STEPS; ++t) {
        const float* xt = x + (size_t)t * BATCH * F0;
        float* spk_out  = out + (size_t)t * BATCH * F3;

        lif_gemm_kernel<64, 4><<<grid_l0, block>>>(xt, w0, b0, m0, s0, F0, F1);
        lif_gemm_kernel<64, 4><<<grid_l1, block>>>(s0, w1, b1, m1, s1, F1, F2);
        lif_gemm_kernel<32, 2><<<grid_l2, block>>>(s1, w2, b2, m2, spk_out, F2, F3);
    }

    // Final membrane of last layer, appended after the spike record.
    const long long mem_off = (long long)T_STEPS * BATCH * F3;
    if ((long long)out_size >= mem_off + (long long)BATCH * F3) {
        copy_final_mem_kernel<<<(BATCH * F3 + 255) / 256, 256>>>(out + mem_off);
    }
}

// round 6
// speedup vs baseline: 1.0002x; 1.0002x over previous
#include <cuda_runtime.h>

// ---------------------------------------------------------------------------
// SNN forward: 25 timesteps, 3 LIF-linear layers (1024->2048->2048->1024),
// batch 256. fp32 FFMA GEMM with fused LIF epilogue.
//
// Output layout (flattened tuple from reference):
//   [0, 25*256*1024)              : spike record of last layer, (T,B,1024)
//   [25*256*1024, +256*1024)      : final membrane of last layer, (B,1024)
// ---------------------------------------------------------------------------

constexpr int T_STEPS = 25;
constexpr int BATCH   = 256;
constexpr int F0 = 1024, F1 = 2048, F2 = 2048, F3 = 1024;

// Persistent scratch (no cudaMalloc allowed): membranes + inter-layer spikes.
__device__ float g_m0[BATCH * F1];
__device__ float g_m1[BATCH * F2];
__device__ float g_m2[BATCH * F3];
__device__ float g_s0[BATCH * F1];
__device__ float g_s1[BATCH * F2];

__global__ void zero_mems_kernel() {
    int idx = blockIdx.x * blockDim.x + threadIdx.x;
    int stride = gridDim.x * blockDim.x;
    for (int i = idx; i < BATCH * F1; i += stride) g_m0[i] = 0.0f;
    for (int i = idx; i < BATCH * F2; i += stride) g_m1[i] = 0.0f;
    for (int i = idx; i < BATCH * F3; i += stride) g_m2[i] = 0.0f;
}

__global__ void copy_final_mem_kernel(float* __restrict__ dst) {
    int i = blockIdx.x * blockDim.x + threadIdx.x;
    if (i < BATCH * F3) dst[i] = g_m2[i];
}

// ---------------------------------------------------------------------------
// Fused GEMM + LIF.
//   cur[b,n] = sum_k A[b,k] * W[n,k] + bias[n]       (A: (BATCH,K), W: (N,K))
//   m = 0.9*m + cur ; s = (m > 1) ; m -= s
// Tile: BM=64 x BN x BK=16, 256 threads, TMxTN register micro-tile.
// ---------------------------------------------------------------------------
template <int BN, int TN>
__global__ __launch_bounds__(256)
void lif_gemm_kernel(const float* __restrict__ A,
                     const float* __restrict__ W,
                     const float* __restrict__ bias,
                     float* __restrict__ mem,
                     float* __restrict__ spk,
                     int K, int N)
{
    constexpr int BM = 64, BK = 16, TM = 4, THREADS = 256;
    constexpr int TX = BN / TN;          // threads along n
    constexpr int TY = THREADS / TX;     // threads along m
    static_assert(TY * TM == BM, "tile mismatch");
    constexpr int PAD = 4;               // keeps float4 alignment (stride mult of 4)

    __shared__ float As[BK][BM + PAD];   // k-major (transposed)
    __shared__ float Bs[BK][BN + PAD];

    const int tid = threadIdx.x;
    const int tx = tid % TX;
    const int ty = tid / TX;
    const int bm = blockIdx.y * BM;
    const int bn = blockIdx.x * BN;

    // ---- A tile loader: 64x16 floats, one float4 along k per thread ----
    const int a_row = tid >> 2;          // 0..63
    const int a_kc  = (tid & 3) << 2;    // 0,4,8,12
    const float* a_ptr = A + (size_t)(bm + a_row) * K + a_kc;

    // ---- B tile loader: BNx16 floats ----
    constexpr int B_PER = BN * BK / THREADS;   // 4 (BN=64) or 2 (BN=32)
    int b_row, b_kc;
    if constexpr (B_PER == 4) { b_row = tid >> 2; b_kc = (tid & 3) << 2; }
    else                      { b_row = tid >> 3; b_kc = (tid & 7) << 1; }
    const float* b_ptr = W + (size_t)(bn + b_row) * K + b_kc;

    float acc[TM][TN];
    #pragma unroll
    for (int i = 0; i < TM; i++)
        #pragma unroll
        for (int j = 0; j < TN; j++) acc[i][j] = 0.0f;

    const int ktiles = K / BK;

    // Prefetch tile 0 into registers
    float4 a_reg = *reinterpret_cast<const float4*>(a_ptr);
    float4 b_reg4;
    float2 b_reg2;
    if constexpr (B_PER == 4) b_reg4 = *reinterpret_cast<const float4*>(b_ptr);
    else                      b_reg2 = *reinterpret_cast<const float2*>(b_ptr);

    // Store tile 0 to smem (transposed)
    As[a_kc + 0][a_row] = a_reg.x;
    As[a_kc + 1][a_row] = a_reg.y;
    As[a_kc + 2][a_row] = a_reg.z;
    As[a_kc + 3][a_row] = a_reg.w;
    if constexpr (B_PER == 4) {
        Bs[b_kc + 0][b_row] = b_reg4.x;
        Bs[b_kc + 1][b_row] = b_reg4.y;
        Bs[b_kc + 2][b_row] = b_reg4.z;
        Bs[b_kc + 3][b_row] = b_reg4.w;
    } else {
        Bs[b_kc + 0][b_row] = b_reg2.x;
        Bs[b_kc + 1][b_row] = b_reg2.y;
    }
    __syncthreads();

    for (int kt = 1; kt <= ktiles; ++kt) {
        // Prefetch next tile (hidden under compute below)
        if (kt < ktiles) {
            a_reg = *reinterpret_cast<const float4*>(a_ptr + kt * BK);
            if constexpr (B_PER == 4)
                b_reg4 = *reinterpret_cast<const float4*>(b_ptr + kt * BK);
            else
                b_reg2 = *reinterpret_cast<const float2*>(b_ptr + kt * BK);
        }

        // Compute current tile from smem
        #pragma unroll
        for (int k = 0; k < BK; ++k) {
            float4 av = *reinterpret_cast<const float4*>(&As[k][ty * TM]);
            float a[TM] = {av.x, av.y, av.z, av.w};
            float b[TN];
            if constexpr (TN == 4) {
                float4 bv = *reinterpret_cast<const float4*>(&Bs[k][tx * TN]);
                b[0] = bv.x; b[1] = bv.y; b[2] = bv.z; b[3] = bv.w;
            } else {
                float2 bv = *reinterpret_cast<const float2*>(&Bs[k][tx * TN]);
                b[0] = bv.x; b[1] = bv.y;
            }
            #pragma unroll
            for (int i = 0; i < TM; i++)
                #pragma unroll
                for (int j = 0; j < TN; j++)
                    acc[i][j] += a[i] * b[j];
        }
        __syncthreads();

        if (kt < ktiles) {
            As[a_kc + 0][a_row] = a_reg.x;
            As[a_kc + 1][a_row] = a_reg.y;
            As[a_kc + 2][a_row] = a_reg.z;
            As[a_kc + 3][a_row] = a_reg.w;
            if constexpr (B_PER == 4) {
                Bs[b_kc + 0][b_row] = b_reg4.x;
                Bs[b_kc + 1][b_row] = b_reg4.y;
                Bs[b_kc + 2][b_row] = b_reg4.z;
                Bs[b_kc + 3][b_row] = b_reg4.w;
            } else {
                Bs[b_kc + 0][b_row] = b_reg2.x;
                Bs[b_kc + 1][b_row] = b_reg2.y;
            }
            __syncthreads();
        }
    }

    // ---- Fused LIF epilogue ----
    #pragma unroll
    for (int i = 0; i < TM; i++) {
        const int row = bm + ty * TM + i;
        #pragma unroll
        for (int j = 0; j < TN; j++) {
            const int col = bn + tx * TN + j;
            const size_t idx = (size_t)row * N + col;
            float cur = acc[i][j] + __ldg(&bias[col]);
            float m = 0.9f * mem[idx] + cur;
            float s = (m > 1.0f) ? 1.0f : 0.0f;   // spike(m - 1): sign-exact vs ref
            mem[idx] = m - s;                     // subtract reset (threshold=1)
            spk[idx] = s;
        }
    }
}

extern "C" void kernel_launch(void* const* d_in, const int* in_sizes, int n_in,
                              void* d_out, int out_size)
{
    (void)in_sizes; (void)n_in;
    const float* x  = (const float*)d_in[0];   // (25,256,1024)
    const float* w0 = (const float*)d_in[1];   // (2048,1024)
    const float* b0 = (const float*)d_in[2];   // (2048)
    const float* w1 = (const float*)d_in[3];   // (2048,2048)
    const float* b1 = (const float*)d_in[4];   // (2048)
    const float* w2 = (const float*)d_in[5];   // (1024,2048)
    const float* b2 = (const float*)d_in[6];   // (1024)
    float* out = (float*)d_out;

    float *m0, *m1, *m2, *s0, *s1;
    cudaGetSymbolAddress((void**)&m0, g_m0);
    cudaGetSymbolAddress((void**)&m1, g_m1);
    cudaGetSymbolAddress((void**)&m2, g_m2);
    cudaGetSymbolAddress((void**)&s0, g_s0);
    cudaGetSymbolAddress((void**)&s1, g_s1);

    zero_mems_kernel<<<512, 256>>>();

    const dim3 block(256);
    const dim3 grid_l0(F1 / 64, BATCH / 64);   // 32 x 4 = 128 CTAs
    const dim3 grid_l1(F2 / 64, BATCH / 64);   // 32 x 4 = 128 CTAs
    const dim3 grid_l2(F3 / 32, BATCH / 64);   // 32 x 4 = 128 CTAs

    for (int t = 0; t < T_STEPS; ++t) {
        const float* xt = x + (size_t)t * BATCH * F0;
        float* spk_out  = out + (size_t)t * BATCH * F3;

        lif_gemm_kernel<64, 4><<<grid_l0, block>>>(xt, w0, b0, m0, s0, F0, F1);
        lif_gemm_kernel<64, 4><<<grid_l1, block>>>(s0, w1, b1, m1, s1, F1, F2);
        lif_gemm_kernel<32, 2><<<grid_l2, block>>>(s1, w2, b2, m2, spk_out, F2, F3);
    }

    // Final membrane of last layer, appended after the spike record.
    const long long mem_off = (long long)T_STEPS * BATCH * F3;
    if ((long long)out_size >= mem_off + (long long)BATCH * F3) {
        copy_final_mem_kernel<<<(BATCH * F3 + 255) / 256, 256>>>(out + mem_off);
    }
}

// round 9
// speedup vs baseline: 1.0388x; 1.0386x over previous
#include <cuda_runtime.h>
#include <cstdint>

// ---------------------------------------------------------------------------
// SNN forward — fp32 bit-exact-chain edition (same arithmetic as the passing
// R6 kernel: per-output single fp32 FMA chain over ascending k).
//   * packed fma.rn.f32x2: two independent IEEE-correct fp32 FMAs per instr
//   * layer-0 currents for all 25 steps hoisted into one full-chip GEMM
//   * BM=32 tiles -> 256 CTAs for the per-step layers (occupancy fix)
// Output: [0, 25*256*1024) layer-2 spike record; then (256*1024) final mem2.
// ---------------------------------------------------------------------------

constexpr int T_STEPS = 25;
constexpr int BATCH   = 256;
constexpr int F0 = 1024, F1 = 2048, F2 = 2048, F3 = 1024;

__device__ float g_cur0[T_STEPS * BATCH * F1];   // hoisted layer-0 currents (+bias)
__device__ float g_m0[BATCH * F1];
__device__ float g_m1[BATCH * F2];
__device__ float g_m2[BATCH * F3];
__device__ float g_s0[BATCH * F1];               // layer-0 spikes (fp32 0/1)
__device__ float g_s1[BATCH * F2];               // layer-1 spikes

// ----- packed f32x2 helpers (two independent correctly-rounded fp32 FMAs) ---
__device__ __forceinline__ unsigned long long pk2(float x, float y) {
    unsigned long long r;
    asm("mov.b64 %0, {%1, %2};" : "=l"(r) : "f"(x), "f"(y));
    return r;
}
__device__ __forceinline__ void upk2(float& x, float& y, unsigned long long v) {
    asm("mov.b64 {%0, %1}, %2;" : "=f"(x), "=f"(y) : "l"(v));
}
#define FMA2(acc, a, b) \
    asm("fma.rn.f32x2 %0, %1, %2, %0;" : "+l"(acc) : "l"(a), "l"(b))

// ----- small kernels ---------------------------------------------------------
__global__ void zero_mems_kernel() {
    int idx = blockIdx.x * blockDim.x + threadIdx.x;
    int stride = gridDim.x * blockDim.x;
    for (int i = idx; i < BATCH * F1; i += stride) g_m0[i] = 0.0f;
    for (int i = idx; i < BATCH * F2; i += stride) g_m1[i] = 0.0f;
    for (int i = idx; i < BATCH * F3; i += stride) g_m2[i] = 0.0f;
}

// per-step layer-0 LIF on precomputed exact fp32 currents
__global__ void lif0_kernel(const float4* __restrict__ cur_t) {
    int i = blockIdx.x * blockDim.x + threadIdx.x;
    if (i >= (BATCH * F1) / 4) return;
    float4 cur = cur_t[i];
    float4 m = reinterpret_cast<float4*>(g_m0)[i];
    float4 s;
    m.x = 0.9f * m.x + cur.x; s.x = (m.x > 1.0f) ? 1.0f : 0.0f; m.x -= s.x;
    m.y = 0.9f * m.y + cur.y; s.y = (m.y > 1.0f) ? 1.0f : 0.0f; m.y -= s.y;
    m.z = 0.9f * m.z + cur.z; s.z = (m.z > 1.0f) ? 1.0f : 0.0f; m.z -= s.z;
    m.w = 0.9f * m.w + cur.w; s.w = (m.w > 1.0f) ? 1.0f : 0.0f; m.w -= s.w;
    reinterpret_cast<float4*>(g_m0)[i] = m;
    reinterpret_cast<float4*>(g_s0)[i] = s;
}

__global__ void copy_final_mem_kernel(float* __restrict__ dst) {
    int i = blockIdx.x * blockDim.x + threadIdx.x;
    if (i < BATCH * F3) dst[i] = g_m2[i];
}

// ---------------------------------------------------------------------------
// fp32 GEMM + LIF, packed FFMA2.
//   cur[b,n] = sum_k A[b,k]*W[n,k] + bias[n]   (single FMA chain, k ascending)
// Tile: BM=32 x BN x BK=32, 128 threads, micro-tile TM=4 x TN.
// EPI: 0 = store cur (hoisted layer 0)
//      1 = LIF, spikes -> spk (fp32)
//      2 = LIF, spikes -> spk (fp32, final layer into d_out)
// ---------------------------------------------------------------------------
template <int BN, int TN, int EPI>
__global__ __launch_bounds__(128)
void gemm_lif_kernel(const float* __restrict__ A,
                     const float* __restrict__ W,
                     const float* __restrict__ bias,
                     float* __restrict__ mem,
                     float* __restrict__ spk,
                     int K, int N)
{
    constexpr int BM = 32, BK = 32, THREADS = 128, TM = 4;
    constexpr int TX = BN / TN;               // 16
    constexpr int TY = THREADS / TX;          // 8
    static_assert(TY * TM == BM, "tile mismatch");
    constexpr int A_CH = BM * BK / (4 * THREADS);   // 2
    constexpr int B_CH = BN * BK / (4 * THREADS);   // 4 (BN=64) or 2 (BN=32)
    constexpr int NP = TN / 2;                // f32x2 pairs per row

    __shared__ float As[2][BK][BM + 4];
    __shared__ float Bs[2][BK][BN + 4];

    const int tid = threadIdx.x;
    const int tx = tid % TX;
    const int ty = tid / TX;
    const int bn = blockIdx.x * BN;
    const int bm = blockIdx.y * BM;

    // loaders: chunk ch -> row = ch>>3, kcol = (ch&7)*4  (BK/4 = 8 chunks/row)
    const float* a_base = A + (size_t)(bm + (tid >> 3)) * K + ((tid & 7) << 2);
    const float* w_base = W + (size_t)(bn + (tid >> 3)) * K + ((tid & 7) << 2);

    unsigned long long acc2[TM][NP];
    #pragma unroll
    for (int i = 0; i < TM; i++)
        #pragma unroll
        for (int p = 0; p < NP; p++) acc2[i][p] = 0ULL;

    const int ktiles = K / BK;

    float4 pa[A_CH], pb[B_CH];

    // prologue: tile 0 -> regs -> smem
    #pragma unroll
    for (int i = 0; i < A_CH; i++)
        pa[i] = *reinterpret_cast<const float4*>(a_base + (size_t)(i * 16) * K);
    #pragma unroll
    for (int i = 0; i < B_CH; i++)
        pb[i] = *reinterpret_cast<const float4*>(w_base + (size_t)(i * 16) * K);

    {
        const int r0 = tid >> 3, c0 = (tid & 7) << 2;
        #pragma unroll
        for (int i = 0; i < A_CH; i++) {
            As[0][c0 + 0][r0 + i * 16] = pa[i].x;
            As[0][c0 + 1][r0 + i * 16] = pa[i].y;
            As[0][c0 + 2][r0 + i * 16] = pa[i].z;
            As[0][c0 + 3][r0 + i * 16] = pa[i].w;
        }
        #pragma unroll
        for (int i = 0; i < B_CH; i++) {
            Bs[0][c0 + 0][r0 + i * 16] = pb[i].x;
            Bs[0][c0 + 1][r0 + i * 16] = pb[i].y;
            Bs[0][c0 + 2][r0 + i * 16] = pb[i].z;
            Bs[0][c0 + 3][r0 + i * 16] = pb[i].w;
        }
    }
    __syncthreads();

    for (int kt = 0; kt < ktiles; ++kt) {
        const int buf = kt & 1;
        // prefetch next tile into registers (hidden under compute)
        if (kt + 1 < ktiles) {
            const int k0 = (kt + 1) * BK;
            #pragma unroll
            for (int i = 0; i < A_CH; i++)
                pa[i] = *reinterpret_cast<const float4*>(a_base + (size_t)(i * 16) * K + k0);
            #pragma unroll
            for (int i = 0; i < B_CH; i++)
                pb[i] = *reinterpret_cast<const float4*>(w_base + (size_t)(i * 16) * K + k0);
        }

        // compute 32 k-steps; chain order strictly ascending in k
        #pragma unroll
        for (int k = 0; k < BK; ++k) {
            float4 av = *reinterpret_cast<const float4*>(&As[buf][k][ty * TM]);
            unsigned long long bp[NP];
            if constexpr (TN == 4) {
                float4 bv = *reinterpret_cast<const float4*>(&Bs[buf][k][tx * TN]);
                bp[0] = pk2(bv.x, bv.y);
                bp[1] = pk2(bv.z, bv.w);
            } else {
                float2 bv = *reinterpret_cast<const float2*>(&Bs[buf][k][tx * TN]);
                bp[0] = pk2(bv.x, bv.y);
            }
            const float am[TM] = {av.x, av.y, av.z, av.w};
            #pragma unroll
            for (int i = 0; i < TM; i++) {
                unsigned long long ad = pk2(am[i], am[i]);
                #pragma unroll
                for (int p = 0; p < NP; p++) FMA2(acc2[i][p], ad, bp[p]);
            }
        }
        __syncthreads();

        if (kt + 1 < ktiles) {
            const int nb = (kt + 1) & 1;
            const int r0 = tid >> 3, c0 = (tid & 7) << 2;
            #pragma unroll
            for (int i = 0; i < A_CH; i++) {
                As[nb][c0 + 0][r0 + i * 16] = pa[i].x;
                As[nb][c0 + 1][r0 + i * 16] = pa[i].y;
                As[nb][c0 + 2][r0 + i * 16] = pa[i].z;
                As[nb][c0 + 3][r0 + i * 16] = pa[i].w;
            }
            #pragma unroll
            for (int i = 0; i < B_CH; i++) {
                Bs[nb][c0 + 0][r0 + i * 16] = pb[i].x;
                Bs[nb][c0 + 1][r0 + i * 16] = pb[i].y;
                Bs[nb][c0 + 2][r0 + i * 16] = pb[i].z;
                Bs[nb][c0 + 3][r0 + i * 16] = pb[i].w;
            }
            __syncthreads();
        }
    }

    // ---- epilogue (identical expressions to the passing R6 kernel) ----
    #pragma unroll
    for (int i = 0; i < TM; i++) {
        const int row = bm + ty * TM + i;
        #pragma unroll
        for (int p = 0; p < NP; p++) {
            float c0, c1;
            upk2(c0, c1, acc2[i][p]);
            const float cc[2] = {c0, c1};
            #pragma unroll
            for (int q = 0; q < 2; q++) {
                const int col = bn + tx * TN + p * 2 + q;
                const size_t idx = (size_t)row * N + col;
                const float cur = cc[q] + __ldg(&bias[col]);
                if (EPI == 0) {
                    spk[idx] = cur;                    // store current
                } else {
                    float m = 0.9f * mem[idx] + cur;
                    float s = (m > 1.0f) ? 1.0f : 0.0f;
                    mem[idx] = m - s;
                    spk[idx] = s;
                }
            }
        }
    }
}

// ---------------------------------------------------------------------------
extern "C" void kernel_launch(void* const* d_in, const int* in_sizes, int n_in,
                              void* d_out, int out_size)
{
    (void)in_sizes; (void)n_in;
    const float* x  = (const float*)d_in[0];   // (25,256,1024)
    const float* w0 = (const float*)d_in[1];   // (2048,1024)
    const float* b0 = (const float*)d_in[2];
    const float* w1 = (const float*)d_in[3];   // (2048,2048)
    const float* b1 = (const float*)d_in[4];
    const float* w2 = (const float*)d_in[5];   // (1024,2048)
    const float* b2 = (const float*)d_in[6];
    float* out = (float*)d_out;

    float *cur0, *m0, *m1, *m2, *s0, *s1;
    cudaGetSymbolAddress((void**)&cur0, g_cur0);
    cudaGetSymbolAddress((void**)&m0, g_m0);
    cudaGetSymbolAddress((void**)&m1, g_m1);
    cudaGetSymbolAddress((void**)&m2, g_m2);
    cudaGetSymbolAddress((void**)&s0, g_s0);
    cudaGetSymbolAddress((void**)&s1, g_s1);
    (void)m0;

    zero_mems_kernel<<<512, 256>>>();

    // Hoisted layer-0 GEMM: all 25 timesteps at once (M = 6400) -> cur0.
    // Per-output FMA chain identical to the per-step version (same k order).
    {
        dim3 grid(F1 / 64, (T_STEPS * BATCH) / 32);   // 32 x 200 = 6400 CTAs
        gemm_lif_kernel<64, 4, 0><<<grid, 128>>>(x, w0, b0, nullptr, cur0, F0, F1);
    }

    const dim3 grid1(F2 / 64, BATCH / 32);   // 32 x 8 = 256 CTAs
    const dim3 grid2(F3 / 32, BATCH / 32);   // 32 x 8 = 256 CTAs

    for (int t = 0; t < T_STEPS; ++t) {
        lif0_kernel<<<(BATCH * F1 / 4 + 255) / 256, 256>>>(
            reinterpret_cast<const float4*>(cur0 + (size_t)t * BATCH * F1));
        gemm_lif_kernel<64, 4, 1><<<grid1, 128>>>(s0, w1, b1, m1, s1, F1, F2);
        float* spk_out = out + (size_t)t * BATCH * F3;
        gemm_lif_kernel<32, 2, 2><<<grid2, 128>>>(s1, w2, b2, m2, spk_out, F2, F3);
    }

    const long long mem_off = (long long)T_STEPS * BATCH * F3;
    if ((long long)out_size >= mem_off + (long long)BATCH * F3) {
        copy_final_mem_kernel<<<(BATCH * F3 + 255) / 256, 256>>>(out + mem_off);
    }
}

// round 10
// speedup vs baseline: 1.1571x; 1.1139x over previous
#include <cuda_runtime.h>
#include <cstdint>

// ---------------------------------------------------------------------------
// SNN forward — fp32 bit-exact-chain, v2.
//   Same per-output fp32 FMA chain (ascending k) as the passing R6/R9 kernels.
//   * fma.rn.f32x2 packed FMAs (two independent IEEE fp32 FMAs per instr)
//   * weights pre-transposed (WT[k][n]) -> cp.async B tiles, no transpose STS
//   * bigger micro-tiles: 8x8 (hoisted layer0), 8x4 (layer1), 4x4 (layer2)
//   * lif0 fused: t=0 into layer0 epilogue, t+1 into layer2 tail
// Output: [0, 25*256*1024) layer-2 spike record; then (256*1024) final mem2.
// ---------------------------------------------------------------------------

constexpr int T_STEPS = 25;
constexpr int BATCH   = 256;
constexpr int F0 = 1024, F1 = 2048, F2 = 2048, F3 = 1024;
constexpr int BK = 32;

__device__ float g_wt0[F0 * F1];                 // W0^T  [k][n]
__device__ float g_wt1[F1 * F2];                 // W1^T
__device__ float g_wt2[F2 * F3];                 // W2^T
__device__ float g_cur0[T_STEPS * BATCH * F1];   // hoisted layer-0 currents
__device__ float g_m0[BATCH * F1];
__device__ float g_m1[BATCH * F2];
__device__ float g_m2[BATCH * F3];
__device__ float g_s0[BATCH * F1];
__device__ float g_s1[BATCH * F2];

// ----- packed f32x2 helpers ---------------------------------------------------
__device__ __forceinline__ unsigned long long pk2(float x, float y) {
    unsigned long long r;
    asm("mov.b64 %0, {%1, %2};" : "=l"(r) : "f"(x), "f"(y));
    return r;
}
__device__ __forceinline__ void upk2(float& x, float& y, unsigned long long v) {
    asm("mov.b64 {%0, %1}, %2;" : "=f"(x), "=f"(y) : "l"(v));
}
#define FMA2(acc, a, b) \
    asm("fma.rn.f32x2 %0, %1, %2, %0;" : "+l"(acc) : "l"(a), "l"(b))

#define CP_ASYNC16(dst, src) \
    asm volatile("cp.async.cg.shared.global [%0], [%1], 16;\n" :: "r"(dst), "l"(src))
#define CP_COMMIT() asm volatile("cp.async.commit_group;\n")
#define CP_WAIT0()  asm volatile("cp.async.wait_group 0;\n")

__device__ __forceinline__ uint32_t cvta_s(const void* p) {
    return (uint32_t)__cvta_generic_to_shared(p);
}

// ----- prep kernels ------------------------------------------------------------
__global__ void zero_mems_kernel() {
    int idx = blockIdx.x * blockDim.x + threadIdx.x;
    int stride = gridDim.x * blockDim.x;
    for (int i = idx; i < BATCH * F2; i += stride) g_m1[i] = 0.0f;
    for (int i = idx; i < BATCH * F3; i += stride) g_m2[i] = 0.0f;
}

// dst[C][R] = src[R][C], R,C multiples of 32
__global__ void transpose_kernel(const float* __restrict__ src,
                                 float* __restrict__ dst, int R, int C) {
    __shared__ float tile[32][33];
    int c0 = blockIdx.x * 32, r0 = blockIdx.y * 32;
    int tx = threadIdx.x, ty = threadIdx.y;          // 32 x 8
    #pragma unroll
    for (int j = 0; j < 32; j += 8)
        tile[ty + j][tx] = src[(size_t)(r0 + ty + j) * C + c0 + tx];
    __syncthreads();
    #pragma unroll
    for (int j = 0; j < 32; j += 8)
        dst[(size_t)(c0 + ty + j) * R + r0 + tx] = tile[tx][ty + j];
}

__global__ void copy_final_mem_kernel(float* __restrict__ dst) {
    int i = blockIdx.x * blockDim.x + threadIdx.x;
    if (i < BATCH * F3) dst[i] = g_m2[i];
}

// ---------------------------------------------------------------------------
// GEMM + LIF.  cur[m,n] = sum_k A[m,k]*WT[k,n] + bias[n]  (chain, k ascending)
// 128 threads; CTA tile BM x BN x BK=32; per-thread TM x TN; f32x2 accumulators.
// EPI 0: store cur (hoisted layer0) + fused lif0 for t=0 rows (m<BATCH)
// EPI 1: LIF -> mem/spk (layer1)
// EPI 2: LIF -> mem/spk (layer2, spk=output) + fused lif0 for next step
// ---------------------------------------------------------------------------
template <int BM, int BN, int TM, int TN, int EPI>
__global__ __launch_bounds__(128)
void gemm_lif(const float* __restrict__ A,
              const float* __restrict__ WT,
              const float* __restrict__ bias,
              float* __restrict__ mem,
              float* __restrict__ spk,
              const float* __restrict__ cur0_next,
              int K, int N)
{
    constexpr int TX = BN / TN, TY = BM / TM;
    static_assert(TX * TY == 128, "thread grid");
    constexpr int AC = BM / 16;          // A float4 chunks per thread
    constexpr int BNC = BN / 4;          // B float4 chunks per k-row
    constexpr int RP = 128 / BNC;        // B k-rows loaded per pass
    constexpr int BC = BK / RP;          // B passes per thread
    constexpr int NP = TN / 2;

    __shared__ float As[2][BK][BM + 4];
    __shared__ float Bs[2][BK][BN + 4];

    const int tid = threadIdx.x;
    const int tx = tid % TX, ty = tid / TX;
    const int bn = blockIdx.x * BN, bm = blockIdx.y * BM;

    // A loader: m = (tid&15)+16i, k-chunk = tid>>4  (STS banks (4k+m)%32: conflict-free)
    const int am  = tid & 15;
    const int akc = tid >> 4;
    // B loader (WT k-major): chunk nc = tid%BNC, row kr = tid/BNC + RP*i
    const int bnc = tid % BNC;
    const int bkr = tid / BNC;

    unsigned long long acc2[TM][NP];
    #pragma unroll
    for (int i = 0; i < TM; i++)
        #pragma unroll
        for (int p = 0; p < NP; p++) acc2[i][p] = 0ULL;

    const int ktiles = K / BK;
    float4 pa[AC];

    // ---- prologue: tile 0 ----
    #pragma unroll
    for (int i = 0; i < BC; i++) {
        int kr = bkr + RP * i;
        CP_ASYNC16(cvta_s(&Bs[0][kr][bnc * 4]),
                   WT + (size_t)kr * N + bn + bnc * 4);
    }
    CP_COMMIT();
    #pragma unroll
    for (int i = 0; i < AC; i++)
        pa[i] = *reinterpret_cast<const float4*>(A + (size_t)(bm + am + 16 * i) * K + akc * 4);
    #pragma unroll
    for (int i = 0; i < AC; i++) {
        As[0][akc * 4 + 0][am + 16 * i] = pa[i].x;
        As[0][akc * 4 + 1][am + 16 * i] = pa[i].y;
        As[0][akc * 4 + 2][am + 16 * i] = pa[i].z;
        As[0][akc * 4 + 3][am + 16 * i] = pa[i].w;
    }
    CP_WAIT0();
    __syncthreads();

    for (int kt = 0; kt < ktiles; ++kt) {
        const int buf = kt & 1;
        if (kt + 1 < ktiles) {
            const int k0 = (kt + 1) * BK;
            #pragma unroll
            for (int i = 0; i < BC; i++) {
                int kr = bkr + RP * i;
                CP_ASYNC16(cvta_s(&Bs[buf ^ 1][kr][bnc * 4]),
                           WT + (size_t)(k0 + kr) * N + bn + bnc * 4);
            }
            CP_COMMIT();
            #pragma unroll
            for (int i = 0; i < AC; i++)
                pa[i] = *reinterpret_cast<const float4*>(
                    A + (size_t)(bm + am + 16 * i) * K + k0 + akc * 4);
        }

        // ---- compute 32 k-steps (ascending k; chain per output) ----
        #pragma unroll
        for (int k = 0; k < BK; ++k) {
            float4 av[TM / 4];
            #pragma unroll
            for (int u = 0; u < TM / 4; u++)
                av[u] = *reinterpret_cast<const float4*>(&As[buf][k][ty * TM + 4 * u]);
            unsigned long long bp[NP];
            #pragma unroll
            for (int v = 0; v < TN / 4; v++) {
                float4 bv = *reinterpret_cast<const float4*>(&Bs[buf][k][tx * TN + 4 * v]);
                bp[2 * v + 0] = pk2(bv.x, bv.y);
                bp[2 * v + 1] = pk2(bv.z, bv.w);
            }
            #pragma unroll
            for (int u = 0; u < TM / 4; u++) {
                const float am4[4] = {av[u].x, av[u].y, av[u].z, av[u].w};
                #pragma unroll
                for (int l = 0; l < 4; l++) {
                    unsigned long long ad = pk2(am4[l], am4[l]);
                    #pragma unroll
                    for (int p = 0; p < NP; p++) FMA2(acc2[u * 4 + l][p], ad, bp[p]);
                }
            }
        }

        if (kt + 1 < ktiles) {
            const int nb = buf ^ 1;
            #pragma unroll
            for (int i = 0; i < AC; i++) {
                As[nb][akc * 4 + 0][am + 16 * i] = pa[i].x;
                As[nb][akc * 4 + 1][am + 16 * i] = pa[i].y;
                As[nb][akc * 4 + 2][am + 16 * i] = pa[i].z;
                As[nb][akc * 4 + 3][am + 16 * i] = pa[i].w;
            }
        }
        CP_WAIT0();
        __syncthreads();
    }

    // ---- epilogue (expressions identical to the passing R9 kernel) ----
    #pragma unroll
    for (int i = 0; i < TM; i++) {
        const int row = bm + ty * TM + i;
        #pragma unroll
        for (int p = 0; p < NP; p++) {
            float c0, c1;
            upk2(c0, c1, acc2[i][p]);
            const float cc[2] = {c0, c1};
            #pragma unroll
            for (int q = 0; q < 2; q++) {
                const int col = bn + tx * TN + p * 2 + q;
                const size_t idx = (size_t)row * N + col;
                const float cur = cc[q] + __ldg(&bias[col]);
                if (EPI == 0) {
                    spk[idx] = cur;                         // current record
                    if (row < BATCH) {                      // fused lif0 for t=0
                        float m = 0.9f * 0.0f + cur;        // m0 starts at 0
                        float s = (m > 1.0f) ? 1.0f : 0.0f;
                        g_m0[(size_t)row * N + col] = m - s;
                        g_s0[(size_t)row * N + col] = s;
                    }
                } else {
                    float m = 0.9f * mem[idx] + cur;
                    float s = (m > 1.0f) ? 1.0f : 0.0f;
                    mem[idx] = m - s;
                    spk[idx] = s;
                }
            }
        }
    }

    // ---- fused lif0 for the NEXT timestep (layer2 only) ----
    if (EPI == 2 && cur0_next != nullptr) {
        const int nthreads = gridDim.x * gridDim.y * 128;
        int gid = (blockIdx.y * gridDim.x + blockIdx.x) * 128 + tid;
        const float4* c4 = reinterpret_cast<const float4*>(cur0_next);
        float4* m4 = reinterpret_cast<float4*>(g_m0);
        float4* s4 = reinterpret_cast<float4*>(g_s0);
        for (int i = gid; i < (BATCH * F1) / 4; i += nthreads) {
            float4 cur = c4[i];
            float4 m = m4[i];
            float4 s;
            m.x = 0.9f * m.x + cur.x; s.x = (m.x > 1.0f) ? 1.0f : 0.0f; m.x -= s.x;
            m.y = 0.9f * m.y + cur.y; s.y = (m.y > 1.0f) ? 1.0f : 0.0f; m.y -= s.y;
            m.z = 0.9f * m.z + cur.z; s.z = (m.z > 1.0f) ? 1.0f : 0.0f; m.z -= s.z;
            m.w = 0.9f * m.w + cur.w; s.w = (m.w > 1.0f) ? 1.0f : 0.0f; m.w -= s.w;
            m4[i] = m;
            s4[i] = s;
        }
    }
}

// ---------------------------------------------------------------------------
extern "C" void kernel_launch(void* const* d_in, const int* in_sizes, int n_in,
                              void* d_out, int out_size)
{
    (void)in_sizes; (void)n_in;
    const float* x  = (const float*)d_in[0];   // (25,256,1024)
    const float* w0 = (const float*)d_in[1];   // (2048,1024)
    const float* b0 = (const float*)d_in[2];
    const float* w1 = (const float*)d_in[3];   // (2048,2048)
    const float* b1 = (const float*)d_in[4];
    const float* w2 = (const float*)d_in[5];   // (1024,2048)
    const float* b2 = (const float*)d_in[6];
    float* out = (float*)d_out;

    float *wt0, *wt1, *wt2, *cur0, *m1, *m2, *s0, *s1;
    cudaGetSymbolAddress((void**)&wt0, g_wt0);
    cudaGetSymbolAddress((void**)&wt1, g_wt1);
    cudaGetSymbolAddress((void**)&wt2, g_wt2);
    cudaGetSymbolAddress((void**)&cur0, g_cur0);
    cudaGetSymbolAddress((void**)&m1, g_m1);
    cudaGetSymbolAddress((void**)&m2, g_m2);
    cudaGetSymbolAddress((void**)&s0, g_s0);
    cudaGetSymbolAddress((void**)&s1, g_s1);

    // prep: transposes + membrane zeroing
    {
        dim3 blk(32, 8);
        transpose_kernel<<<dim3(F0 / 32, F1 / 32), blk>>>(w0, wt0, F1, F0);
        transpose_kernel<<<dim3(F1 / 32, F2 / 32), blk>>>(w1, wt1, F2, F1);
        transpose_kernel<<<dim3(F2 / 32, F3 / 32), blk>>>(w2, wt2, F3, F2);
        zero_mems_kernel<<<512, 256>>>();
    }

    // hoisted layer-0 GEMM: M = 25*256 = 6400 (also does lif0 for t=0)
    {
        dim3 grid(F1 / 128, (T_STEPS * BATCH) / 64);     // 16 x 100
        gemm_lif<64, 128, 8, 8, 0><<<grid, 128>>>(
            x, wt0, b0, nullptr, cur0, nullptr, F0, F1);
    }

    const dim3 grid1(F2 / 64, BATCH / 64);   // 32 x 4  = 128 CTAs
    const dim3 grid2(F3 / 64, BATCH / 32);   // 16 x 8  = 128 CTAs

    for (int t = 0; t < T_STEPS; ++t) {
        gemm_lif<64, 64, 8, 4, 1><<<grid1, 128>>>(
            s0, wt1, b1, m1, s1, nullptr, F1, F2);
        float* spk_out = out + (size_t)t * BATCH * F3;
        const float* nxt = (t + 1 < T_STEPS)
                         ? cur0 + (size_t)(t + 1) * BATCH * F1 : nullptr;
        gemm_lif<32, 64, 4, 4, 2><<<grid2, 128>>>(
            s1, wt2, b2, m2, spk_out, nxt, F2, F3);
    }

    const long long mem_off = (long long)T_STEPS * BATCH * F3;
    if ((long long)out_size >= mem_off + (long long)BATCH * F3) {
        copy_final_mem_kernel<<<(BATCH * F3 + 255) / 256, 256>>>(out + mem_off);
    }
}

// round 11
// speedup vs baseline: 1.2937x; 1.1181x over previous
#include <cuda_runtime.h>
#include <cstdint>

// ---------------------------------------------------------------------------
// SNN forward — fp32 bit-exact-chain, v3.
//   Same per-output fp32 FMA chain (ascending k) as passing R6/R9/R10 kernels.
//   * fma.rn.f32x2 packed FMAs
//   * weights pre-transposed; cp.async B tiles
//   * layer-0 hoisted into one big GEMM (M=6400) with lif0(t=0) fused
//   * NEW: layer2(t) and layer1(t+1) fused into ONE 384-CTA launch per step
//     (double-buffered s0/s1), lif0(t+2) tail-fused. 1 launch per step.
// Output: [0, 25*256*1024) layer-2 spike record; then (256*1024) final mem2.
// ---------------------------------------------------------------------------

constexpr int T_STEPS = 25;
constexpr int BATCH   = 256;
constexpr int F0 = 1024, F1 = 2048, F2 = 2048, F3 = 1024;
constexpr int BK = 32;

__device__ float g_wt0[F0 * F1];                 // W0^T [k][n]
__device__ float g_wt1[F1 * F2];
__device__ float g_wt2[F2 * F3];
__device__ float g_cur0[T_STEPS * BATCH * F1];   // hoisted layer-0 currents
__device__ float g_m0[BATCH * F1];
__device__ float g_m1[BATCH * F2];
__device__ float g_m2[BATCH * F3];
__device__ float g_s0[2][BATCH * F1];            // double-buffered spikes
__device__ float g_s1[2][BATCH * F2];

// ----- packed f32x2 helpers ---------------------------------------------------
__device__ __forceinline__ unsigned long long pk2(float x, float y) {
    unsigned long long r;
    asm("mov.b64 %0, {%1, %2};" : "=l"(r) : "f"(x), "f"(y));
    return r;
}
__device__ __forceinline__ void upk2(float& x, float& y, unsigned long long v) {
    asm("mov.b64 {%0, %1}, %2;" : "=f"(x), "=f"(y) : "l"(v));
}
#define FMA2(acc, a, b) \
    asm("fma.rn.f32x2 %0, %1, %2, %0;" : "+l"(acc) : "l"(a), "l"(b))

#define CP_ASYNC16(dst, src) \
    asm volatile("cp.async.cg.shared.global [%0], [%1], 16;\n" :: "r"(dst), "l"(src))
#define CP_COMMIT() asm volatile("cp.async.commit_group;\n")
#define CP_WAIT0()  asm volatile("cp.async.wait_group 0;\n")

__device__ __forceinline__ uint32_t cvta_s(const void* p) {
    return (uint32_t)__cvta_generic_to_shared(p);
}

// ----- prep kernels -------------------------------------------------------------
__global__ void zero_mems_kernel() {
    int idx = blockIdx.x * blockDim.x + threadIdx.x;
    int stride = gridDim.x * blockDim.x;
    for (int i = idx; i < BATCH * F2; i += stride) g_m1[i] = 0.0f;
    for (int i = idx; i < BATCH * F3; i += stride) g_m2[i] = 0.0f;
}

__global__ void transpose_kernel(const float* __restrict__ src,
                                 float* __restrict__ dst, int R, int C) {
    __shared__ float tile[32][33];
    int c0 = blockIdx.x * 32, r0 = blockIdx.y * 32;
    int tx = threadIdx.x, ty = threadIdx.y;          // 32 x 8
    #pragma unroll
    for (int j = 0; j < 32; j += 8)
        tile[ty + j][tx] = src[(size_t)(r0 + ty + j) * C + c0 + tx];
    __syncthreads();
    #pragma unroll
    for (int j = 0; j < 32; j += 8)
        dst[(size_t)(c0 + ty + j) * R + r0 + tx] = tile[tx][ty + j];
}

__global__ void copy_final_mem_kernel(float* __restrict__ dst) {
    int i = blockIdx.x * blockDim.x + threadIdx.x;
    if (i < BATCH * F3) dst[i] = g_m2[i];
}

// ---------------------------------------------------------------------------
// Hoisted layer-0 GEMM (M=6400): BM=64 x BN=128 x BK=32, TM=8 x TN=8, 128 thr.
// Stores currents; fused lif0 for t=0 rows (row < BATCH).
// ---------------------------------------------------------------------------
__global__ __launch_bounds__(128)
void gemm_l0(const float* __restrict__ A,   // x, (6400,1024)
             const float* __restrict__ WT,  // wt0, (1024,2048)
             const float* __restrict__ bias,
             float* __restrict__ cur_out)
{
    constexpr int BM = 64, BN = 128, K = F0, N = F1;
    __shared__ float As[2][BK][BM + 4];
    __shared__ float Bs[2][BK][BN + 4];

    const int tid = threadIdx.x;
    const int tx = tid & 15, ty = tid >> 4;          // TX=16, TY=8
    const int bn = blockIdx.x * BN, bm = blockIdx.y * BM;
    const int am = tid & 15, akc = tid >> 4;         // A: 4 chunks (rows +16i)
    const int bnc = tid & 31, bkr = tid >> 5;        // B: 8 passes (rows +4i)

    unsigned long long acc2[8][4];
    #pragma unroll
    for (int i = 0; i < 8; i++)
        #pragma unroll
        for (int p = 0; p < 4; p++) acc2[i][p] = 0ULL;

    const int ktiles = K / BK;
    float4 pa[4];

    #pragma unroll
    for (int i = 0; i < 8; i++)
        CP_ASYNC16(cvta_s(&Bs[0][bkr + 4 * i][bnc * 4]),
                   WT + (size_t)(bkr + 4 * i) * N + bn + bnc * 4);
    CP_COMMIT();
    #pragma unroll
    for (int i = 0; i < 4; i++)
        pa[i] = *reinterpret_cast<const float4*>(A + (size_t)(bm + am + 16 * i) * K + akc * 4);
    #pragma unroll
    for (int i = 0; i < 4; i++) {
        As[0][akc * 4 + 0][am + 16 * i] = pa[i].x;
        As[0][akc * 4 + 1][am + 16 * i] = pa[i].y;
        As[0][akc * 4 + 2][am + 16 * i] = pa[i].z;
        As[0][akc * 4 + 3][am + 16 * i] = pa[i].w;
    }
    CP_WAIT0();
    __syncthreads();

    for (int kt = 0; kt < ktiles; ++kt) {
        const int buf = kt & 1;
        if (kt + 1 < ktiles) {
            const int k0 = (kt + 1) * BK;
            #pragma unroll
            for (int i = 0; i < 8; i++)
                CP_ASYNC16(cvta_s(&Bs[buf ^ 1][bkr + 4 * i][bnc * 4]),
                           WT + (size_t)(k0 + bkr + 4 * i) * N + bn + bnc * 4);
            CP_COMMIT();
            #pragma unroll
            for (int i = 0; i < 4; i++)
                pa[i] = *reinterpret_cast<const float4*>(
                    A + (size_t)(bm + am + 16 * i) * K + k0 + akc * 4);
        }
        #pragma unroll
        for (int k = 0; k < BK; ++k) {
            float4 av0 = *reinterpret_cast<const float4*>(&As[buf][k][ty * 8]);
            float4 av1 = *reinterpret_cast<const float4*>(&As[buf][k][ty * 8 + 4]);
            float4 bv0 = *reinterpret_cast<const float4*>(&Bs[buf][k][tx * 8]);
            float4 bv1 = *reinterpret_cast<const float4*>(&Bs[buf][k][tx * 8 + 4]);
            unsigned long long bp[4] = {pk2(bv0.x, bv0.y), pk2(bv0.z, bv0.w),
                                        pk2(bv1.x, bv1.y), pk2(bv1.z, bv1.w)};
            const float a8[8] = {av0.x, av0.y, av0.z, av0.w, av1.x, av1.y, av1.z, av1.w};
            #pragma unroll
            for (int l = 0; l < 8; l++) {
                unsigned long long ad = pk2(a8[l], a8[l]);
                #pragma unroll
                for (int p = 0; p < 4; p++) FMA2(acc2[l][p], ad, bp[p]);
            }
        }
        if (kt + 1 < ktiles) {
            const int nb = buf ^ 1;
            #pragma unroll
            for (int i = 0; i < 4; i++) {
                As[nb][akc * 4 + 0][am + 16 * i] = pa[i].x;
                As[nb][akc * 4 + 1][am + 16 * i] = pa[i].y;
                As[nb][akc * 4 + 2][am + 16 * i] = pa[i].z;
                As[nb][akc * 4 + 3][am + 16 * i] = pa[i].w;
            }
        }
        CP_WAIT0();
        __syncthreads();
    }

    #pragma unroll
    for (int i = 0; i < 8; i++) {
        const int row = bm + ty * 8 + i;
        #pragma unroll
        for (int p = 0; p < 4; p++) {
            float c0, c1;
            upk2(c0, c1, acc2[i][p]);
            const float cc[2] = {c0, c1};
            #pragma unroll
            for (int q = 0; q < 2; q++) {
                const int col = bn + tx * 8 + p * 2 + q;
                const size_t idx = (size_t)row * N + col;
                const float cur = cc[q] + __ldg(&bias[col]);
                cur_out[idx] = cur;
                if (row < BATCH) {                    // fused lif0 for t=0
                    float m = 0.9f * 0.0f + cur;
                    float s = (m > 1.0f) ? 1.0f : 0.0f;
                    g_m0[(size_t)row * N + col] = m - s;
                    g_s0[0][(size_t)row * N + col] = s;
                }
            }
        }
    }
}

// ---------------------------------------------------------------------------
// Per-step GEMM tile: BM=32 x BN=64 x BK=32, TM=4 x TN=4, 128 threads.
// Epilogue: LIF (identical expressions to passing kernels).
// ---------------------------------------------------------------------------
__device__ __forceinline__ void gemm_tile32x64(
    float (*As)[BK][36], float (*Bs)[BK][68],
    const float* __restrict__ A, const float* __restrict__ WT,
    const float* __restrict__ bias, float* __restrict__ mem,
    float* __restrict__ spk, int K, int N, int bm, int bn)
{
    const int tid = threadIdx.x;
    const int tx = tid & 15, ty = tid >> 4;          // TX=16, TY=8
    const int am = tid & 15, akc = tid >> 4;         // A: 2 chunks (rows +16i)
    const int bnc = tid & 15, bkr = tid >> 4;        // B: 4 passes (rows +8i)

    unsigned long long acc2[4][2];
    #pragma unroll
    for (int i = 0; i < 4; i++) { acc2[i][0] = 0ULL; acc2[i][1] = 0ULL; }

    const int ktiles = K / BK;
    float4 pa[2];

    #pragma unroll
    for (int i = 0; i < 4; i++)
        CP_ASYNC16(cvta_s(&Bs[0][bkr + 8 * i][bnc * 4]),
                   WT + (size_t)(bkr + 8 * i) * N + bn + bnc * 4);
    CP_COMMIT();
    #pragma unroll
    for (int i = 0; i < 2; i++)
        pa[i] = *reinterpret_cast<const float4*>(A + (size_t)(bm + am + 16 * i) * K + akc * 4);
    #pragma unroll
    for (int i = 0; i < 2; i++) {
        As[0][akc * 4 + 0][am + 16 * i] = pa[i].x;
        As[0][akc * 4 + 1][am + 16 * i] = pa[i].y;
        As[0][akc * 4 + 2][am + 16 * i] = pa[i].z;
        As[0][akc * 4 + 3][am + 16 * i] = pa[i].w;
    }
    CP_WAIT0();
    __syncthreads();

    for (int kt = 0; kt < ktiles; ++kt) {
        const int buf = kt & 1;
        if (kt + 1 < ktiles) {
            const int k0 = (kt + 1) * BK;
            #pragma unroll
            for (int i = 0; i < 4; i++)
                CP_ASYNC16(cvta_s(&Bs[buf ^ 1][bkr + 8 * i][bnc * 4]),
                           WT + (size_t)(k0 + bkr + 8 * i) * N + bn + bnc * 4);
            CP_COMMIT();
            #pragma unroll
            for (int i = 0; i < 2; i++)
                pa[i] = *reinterpret_cast<const float4*>(
                    A + (size_t)(bm + am + 16 * i) * K + k0 + akc * 4);
        }
        #pragma unroll
        for (int k = 0; k < BK; ++k) {
            float4 av = *reinterpret_cast<const float4*>(&As[buf][k][ty * 4]);
            float4 bv = *reinterpret_cast<const float4*>(&Bs[buf][k][tx * 4]);
            unsigned long long bp0 = pk2(bv.x, bv.y), bp1 = pk2(bv.z, bv.w);
            const float a4[4] = {av.x, av.y, av.z, av.w};
            #pragma unroll
            for (int l = 0; l < 4; l++) {
                unsigned long long ad = pk2(a4[l], a4[l]);
                FMA2(acc2[l][0], ad, bp0);
                FMA2(acc2[l][1], ad, bp1);
            }
        }
        if (kt + 1 < ktiles) {
            const int nb = buf ^ 1;
            #pragma unroll
            for (int i = 0; i < 2; i++) {
                As[nb][akc * 4 + 0][am + 16 * i] = pa[i].x;
                As[nb][akc * 4 + 1][am + 16 * i] = pa[i].y;
                As[nb][akc * 4 + 2][am + 16 * i] = pa[i].z;
                As[nb][akc * 4 + 3][am + 16 * i] = pa[i].w;
            }
        }
        CP_WAIT0();
        __syncthreads();
    }

    #pragma unroll
    for (int i = 0; i < 4; i++) {
        const int row = bm + ty * 4 + i;
        #pragma unroll
        for (int p = 0; p < 2; p++) {
            float c0, c1;
            upk2(c0, c1, acc2[i][p]);
            const float cc[2] = {c0, c1};
            #pragma unroll
            for (int q = 0; q < 2; q++) {
                const int col = bn + tx * 4 + p * 2 + q;
                const size_t idx = (size_t)row * N + col;
                const float cur = cc[q] + __ldg(&bias[col]);
                float m = 0.9f * mem[idx] + cur;
                float s = (m > 1.0f) ? 1.0f : 0.0f;
                mem[idx] = m - s;
                spk[idx] = s;
            }
        }
    }
}

// ---------------------------------------------------------------------------
// Combined per-step kernel:
//   CTAs [0,128)  : layer2(t) tiles   (if has_l2)
//   CTAs [.,+256) : layer1(t+1) tiles (if has_l1)
//   tail          : lif0 on cur0_nn -> s0_nn (if non-null)
// All buffer parities disjoint by construction (see launch loop).
// ---------------------------------------------------------------------------
struct StepArgs {
    const float* l1_A;      // s0[(t+1)&1]
    float*       l1_spk;    // s1[(t+1)&1]
    const float* l2_A;      // s1[t&1]
    float*       l2_spk;    // out + t*B*F3
    const float* cur0_nn;   // cur0 + (t+2)*B*F1 (or null)
    float*       s0_nn;     // s0[(t+2)&1]
    int          has_l2;
    int          has_l1;
};

__global__ __launch_bounds__(128)
void step_kernel(StepArgs a,
                 const float* __restrict__ wt1, const float* __restrict__ b1,
                 float* __restrict__ m1,
                 const float* __restrict__ wt2, const float* __restrict__ b2,
                 float* __restrict__ m2)
{
    __shared__ float As[2][BK][36];
    __shared__ float Bs[2][BK][68];

    const int bx = blockIdx.x;
    const bool isL2 = a.has_l2 && (bx < 128);

    if (isL2) {
        // layer2: M=256 (8 m-tiles) x N=1024 (16 n-tiles) = 128 tiles
        const int bn = (bx & 15) * 64;
        const int bm = (bx >> 4) * 32;
        gemm_tile32x64(As, Bs, a.l2_A, wt2, b2, m2, a.l2_spk, F2, F3, bm, bn);
    } else if (a.has_l1) {
        // layer1: M=256 (8 m-tiles) x N=2048 (32 n-tiles) = 256 tiles
        const int id = bx - (a.has_l2 ? 128 : 0);
        const int bn = (id & 31) * 64;
        const int bm = (id >> 5) * 32;
        gemm_tile32x64(As, Bs, a.l1_A, wt1, b1, m1, a.l1_spk, F1, F2, bm, bn);
    }

    // ---- tail: lif0 for step t+2 (buffers disjoint from everything above) ----
    if (a.cur0_nn != nullptr) {
        const int nth = gridDim.x * 128;
        const float4* c4 = reinterpret_cast<const float4*>(a.cur0_nn);
        float4* m4 = reinterpret_cast<float4*>(g_m0);
        float4* s4 = reinterpret_cast<float4*>(a.s0_nn);
        for (int i = bx * 128 + threadIdx.x; i < (BATCH * F1) / 4; i += nth) {
            float4 cur = c4[i];
            float4 m = m4[i];
            float4 s;
            m.x = 0.9f * m.x + cur.x; s.x = (m.x > 1.0f) ? 1.0f : 0.0f; m.x -= s.x;
            m.y = 0.9f * m.y + cur.y; s.y = (m.y > 1.0f) ? 1.0f : 0.0f; m.y -= s.y;
            m.z = 0.9f * m.z + cur.z; s.z = (m.z > 1.0f) ? 1.0f : 0.0f; m.z -= s.z;
            m.w = 0.9f * m.w + cur.w; s.w = (m.w > 1.0f) ? 1.0f : 0.0f; m.w -= s.w;
            m4[i] = m;
            s4[i] = s;
        }
    }
}

// ---------------------------------------------------------------------------
extern "C" void kernel_launch(void* const* d_in, const int* in_sizes, int n_in,
                              void* d_out, int out_size)
{
    (void)in_sizes; (void)n_in;
    const float* x  = (const float*)d_in[0];
    const float* w0 = (const float*)d_in[1];
    const float* b0 = (const float*)d_in[2];
    const float* w1 = (const float*)d_in[3];
    const float* b1 = (const float*)d_in[4];
    const float* w2 = (const float*)d_in[5];
    const float* b2 = (const float*)d_in[6];
    float* out = (float*)d_out;

    float *wt0, *wt1, *wt2, *cur0, *m1, *m2, *s0, *s1;
    cudaGetSymbolAddress((void**)&wt0, g_wt0);
    cudaGetSymbolAddress((void**)&wt1, g_wt1);
    cudaGetSymbolAddress((void**)&wt2, g_wt2);
    cudaGetSymbolAddress((void**)&cur0, g_cur0);
    cudaGetSymbolAddress((void**)&m1, g_m1);
    cudaGetSymbolAddress((void**)&m2, g_m2);
    cudaGetSymbolAddress((void**)&s0, g_s0);
    cudaGetSymbolAddress((void**)&s1, g_s1);
    auto s0b = [&](int i) { return s0 + (size_t)i * BATCH * F1; };
    auto s1b = [&](int i) { return s1 + (size_t)i * BATCH * F2; };

    // prep
    {
        dim3 blk(32, 8);
        transpose_kernel<<<dim3(F0 / 32, F1 / 32), blk>>>(w0, wt0, F1, F0);
        transpose_kernel<<<dim3(F1 / 32, F2 / 32), blk>>>(w1, wt1, F2, F1);
        transpose_kernel<<<dim3(F2 / 32, F3 / 32), blk>>>(w2, wt2, F3, F2);
        zero_mems_kernel<<<512, 256>>>();
    }

    // hoisted layer-0: all currents + lif0(0) -> m0, s0[0]
    gemm_l0<<<dim3(F1 / 128, (T_STEPS * BATCH) / 64), 128>>>(x, wt0, b0, cur0);

    // pre-step: layer1(0) alone + lif0(1) tail
    {
        StepArgs a;
        a.l1_A = s0b(0);  a.l1_spk = s1b(0);
        a.l2_A = nullptr; a.l2_spk = nullptr;
        a.cur0_nn = cur0 + (size_t)1 * BATCH * F1;
        a.s0_nn = s0b(1);
        a.has_l2 = 0; a.has_l1 = 1;
        step_kernel<<<256, 128>>>(a, wt1, b1, m1, wt2, b2, m2);
    }

    // main loop: one launch per step = layer2(t) + layer1(t+1) + lif0(t+2)
    for (int t = 0; t < T_STEPS - 1; ++t) {
        StepArgs a;
        a.l2_A = s1b(t & 1);
        a.l2_spk = out + (size_t)t * BATCH * F3;
        a.l1_A = s0b((t + 1) & 1);
        a.l1_spk = s1b((t + 1) & 1);
        const bool have_next = (t + 2) < T_STEPS;
        a.cur0_nn = have_next ? cur0 + (size_t)(t + 2) * BATCH * F1 : nullptr;
        a.s0_nn = have_next ? s0b((t + 2) & 1) : nullptr;
        a.has_l2 = 1; a.has_l1 = 1;
        step_kernel<<<384, 128>>>(a, wt1, b1, m1, wt2, b2, m2);
    }

    // final: layer2(24) alone
    {
        const int t = T_STEPS - 1;
        StepArgs a;
        a.l2_A = s1b(t & 1);
        a.l2_spk = out + (size_t)t * BATCH * F3;
        a.l1_A = nullptr; a.l1_spk = nullptr;
        a.cur0_nn = nullptr; a.s0_nn = nullptr;
        a.has_l2 = 1; a.has_l1 = 0;
        step_kernel<<<128, 128>>>(a, wt1, b1, m1, wt2, b2, m2);
    }

    const long long mem_off = (long long)T_STEPS * BATCH * F3;
    if ((long long)out_size >= mem_off + (long long)BATCH * F3) {
        copy_final_mem_kernel<<<(BATCH * F3 + 255) / 256, 256>>>(out + mem_off);
    }
}

// round 12
// speedup vs baseline: 1.5150x; 1.1711x over previous
#include <cuda_runtime.h>
#include <cstdint>

// ---------------------------------------------------------------------------
// SNN forward — fp32 bit-exact-chain, v4.
//   Identical per-output fp32 FMA chain (ascending k) to passing R9/R10/R11.
//   * per-warp 32x32 GEMM tiles, micro 8x4, fma.rn.f32x2 (LDS ratio 1.5)
//   * dynamic tile queue via atomicAdd ticket (fixes wave quantization)
//   * transposed layouts (s0T,s1T,m1T,m2T,cur0T) -> cp.async for all tiles
//   * lif0 on the same queue; layer-0 hoisted GEMM with lif0(t=0) fused
// Output: [0, 25*256*1024) layer-2 spike record; then (256*1024) final mem2.
// ---------------------------------------------------------------------------

constexpr int T_STEPS = 25;
constexpr int BATCH   = 256;
constexpr int F0 = 1024, F1 = 2048, F2 = 2048, F3 = 1024;
constexpr int M0 = T_STEPS * BATCH;              // 6400

__device__ float g_wt0[F0 * F1];                 // W0^T [k][n]
__device__ float g_wt1[F1 * F2];                 // W1^T [k][n]
__device__ float g_wt2[F2 * F3];                 // W2^T [k][n]
__device__ float g_cur0T[F1 * M0];               // layer-0 currents, [n][t*B+b]
__device__ float g_m0T[F1 * BATCH];              // membranes, feature-major
__device__ float g_m1T[F2 * BATCH];
__device__ float g_m2T[F3 * BATCH];
__device__ float g_s0T[2][F1 * BATCH];           // spikes, feature-major, dbl-buf
__device__ float g_s1T[2][F2 * BATCH];
__device__ unsigned int g_tick[32];              // per-launch ticket counters

// ----- packed f32x2 helpers ---------------------------------------------------
__device__ __forceinline__ unsigned long long pk2(float x, float y) {
    unsigned long long r;
    asm("mov.b64 %0, {%1, %2};" : "=l"(r) : "f"(x), "f"(y));
    return r;
}
__device__ __forceinline__ void upk2(float& x, float& y, unsigned long long v) {
    asm("mov.b64 {%0, %1}, %2;" : "=f"(x), "=f"(y) : "l"(v));
}
#define FMA2(acc, a, b) \
    asm("fma.rn.f32x2 %0, %1, %2, %0;" : "+l"(acc) : "l"(a), "l"(b))

#define CP_ASYNC16(dst, src) \
    asm volatile("cp.async.cg.shared.global [%0], [%1], 16;\n" :: "r"(dst), "l"(src))
#define CP_COMMIT() asm volatile("cp.async.commit_group;\n")
#define CP_WAIT1()  asm volatile("cp.async.wait_group 1;\n")
#define CP_WAIT0()  asm volatile("cp.async.wait_group 0;\n")

__device__ __forceinline__ uint32_t cvta_s(const void* p) {
    return (uint32_t)__cvta_generic_to_shared(p);
}

// ----- prep kernels ------------------------------------------------------------
__global__ void zero_mems_kernel() {
    int idx = blockIdx.x * blockDim.x + threadIdx.x;
    int stride = gridDim.x * blockDim.x;
    for (int i = idx; i < BATCH * F2; i += stride) g_m1T[i] = 0.0f;
    for (int i = idx; i < BATCH * F3; i += stride) g_m2T[i] = 0.0f;
    if (idx < 32) g_tick[idx] = 0u;
}

__global__ void transpose_kernel(const float* __restrict__ src,
                                 float* __restrict__ dst, int R, int C) {
    __shared__ float tile[32][33];
    int c0 = blockIdx.x * 32, r0 = blockIdx.y * 32;
    int tx = threadIdx.x, ty = threadIdx.y;          // 32 x 8
    #pragma unroll
    for (int j = 0; j < 32; j += 8)
        tile[ty + j][tx] = src[(size_t)(r0 + ty + j) * C + c0 + tx];
    __syncthreads();
    #pragma unroll
    for (int j = 0; j < 32; j += 8)
        dst[(size_t)(c0 + ty + j) * R + r0 + tx] = tile[tx][ty + j];
}

__global__ void copy_final_mem_kernel(float* __restrict__ dst) {
    int i = blockIdx.x * blockDim.x + threadIdx.x;   // i = b*1024 + n
    if (i < BATCH * F3) {
        int b = i >> 10, n = i & 1023;
        dst[i] = g_m2T[(size_t)n * BATCH + b];
    }
}

// ---------------------------------------------------------------------------
// Hoisted layer-0 GEMM (M=6400): BM=64 x BN=128 x BK=32, micro 8x8, 128 thr.
// Writes currents TRANSPOSED (cur0T[n][m]); fused lif0 for t=0 rows.
// ---------------------------------------------------------------------------
__global__ __launch_bounds__(128)
void gemm_l0(const float* __restrict__ A,   // x, (6400,1024) row-major
             const float* __restrict__ WT,  // wt0, (1024,2048)
             const float* __restrict__ bias)
{
    constexpr int BM = 64, BN = 128, BK = 32, K = F0, N = F1;
    __shared__ float As[2][BK][BM + 4];
    __shared__ float Bs[2][BK][BN + 4];

    const int tid = threadIdx.x;
    const int tx = tid & 15, ty = tid >> 4;
    const int bn = blockIdx.x * BN, bm = blockIdx.y * BM;
    const int am = tid & 15, akc = tid >> 4;
    const int bnc = tid & 31, bkr = tid >> 5;

    unsigned long long acc2[8][4];
    #pragma unroll
    for (int i = 0; i < 8; i++)
        #pragma unroll
        for (int p = 0; p < 4; p++) acc2[i][p] = 0ULL;

    const int ktiles = K / BK;
    float4 pa[4];

    #pragma unroll
    for (int i = 0; i < 8; i++)
        CP_ASYNC16(cvta_s(&Bs[0][bkr + 4 * i][bnc * 4]),
                   WT + (size_t)(bkr + 4 * i) * N + bn + bnc * 4);
    CP_COMMIT();
    #pragma unroll
    for (int i = 0; i < 4; i++)
        pa[i] = *reinterpret_cast<const float4*>(A + (size_t)(bm + am + 16 * i) * K + akc * 4);
    #pragma unroll
    for (int i = 0; i < 4; i++) {
        As[0][akc * 4 + 0][am + 16 * i] = pa[i].x;
        As[0][akc * 4 + 1][am + 16 * i] = pa[i].y;
        As[0][akc * 4 + 2][am + 16 * i] = pa[i].z;
        As[0][akc * 4 + 3][am + 16 * i] = pa[i].w;
    }
    CP_WAIT0();
    __syncthreads();

    for (int kt = 0; kt < ktiles; ++kt) {
        const int buf = kt & 1;
        if (kt + 1 < ktiles) {
            const int k0 = (kt + 1) * BK;
            #pragma unroll
            for (int i = 0; i < 8; i++)
                CP_ASYNC16(cvta_s(&Bs[buf ^ 1][bkr + 4 * i][bnc * 4]),
                           WT + (size_t)(k0 + bkr + 4 * i) * N + bn + bnc * 4);
            CP_COMMIT();
            #pragma unroll
            for (int i = 0; i < 4; i++)
                pa[i] = *reinterpret_cast<const float4*>(
                    A + (size_t)(bm + am + 16 * i) * K + k0 + akc * 4);
        }
        #pragma unroll
        for (int k = 0; k < BK; ++k) {
            float4 av0 = *reinterpret_cast<const float4*>(&As[buf][k][ty * 8]);
            float4 av1 = *reinterpret_cast<const float4*>(&As[buf][k][ty * 8 + 4]);
            float4 bv0 = *reinterpret_cast<const float4*>(&Bs[buf][k][tx * 8]);
            float4 bv1 = *reinterpret_cast<const float4*>(&Bs[buf][k][tx * 8 + 4]);
            unsigned long long bp[4] = {pk2(bv0.x, bv0.y), pk2(bv0.z, bv0.w),
                                        pk2(bv1.x, bv1.y), pk2(bv1.z, bv1.w)};
            const float a8[8] = {av0.x, av0.y, av0.z, av0.w, av1.x, av1.y, av1.z, av1.w};
            #pragma unroll
            for (int l = 0; l < 8; l++) {
                unsigned long long ad = pk2(a8[l], a8[l]);
                #pragma unroll
                for (int p = 0; p < 4; p++) FMA2(acc2[l][p], ad, bp[p]);
            }
        }
        if (kt + 1 < ktiles) {
            const int nb = buf ^ 1;
            #pragma unroll
            for (int i = 0; i < 4; i++) {
                As[nb][akc * 4 + 0][am + 16 * i] = pa[i].x;
                As[nb][akc * 4 + 1][am + 16 * i] = pa[i].y;
                As[nb][akc * 4 + 2][am + 16 * i] = pa[i].z;
                As[nb][akc * 4 + 3][am + 16 * i] = pa[i].w;
            }
        }
        CP_WAIT0();
        __syncthreads();
    }

    // epilogue: cur0T[col][row] (+ fused lif0 for t=0 when row < BATCH)
    const int row0 = bm + ty * 8;
    #pragma unroll
    for (int p = 0; p < 4; p++) {
        #pragma unroll
        for (int q = 0; q < 2; q++) {
            const int col = bn + tx * 8 + p * 2 + q;
            const float bcol = __ldg(&bias[col]);
            float v[8];
            #pragma unroll
            for (int i = 0; i < 8; i++) {
                float c0, c1;
                upk2(c0, c1, acc2[i][p]);
                v[i] = (q ? c1 : c0) + bcol;
            }
            float* cp = g_cur0T + (size_t)col * M0 + row0;
            *reinterpret_cast<float4*>(cp)     = make_float4(v[0], v[1], v[2], v[3]);
            *reinterpret_cast<float4*>(cp + 4) = make_float4(v[4], v[5], v[6], v[7]);
            if (bm < BATCH) {                    // t=0 lif0 (m0 starts at 0)
                float mm[8], ss[8];
                #pragma unroll
                for (int i = 0; i < 8; i++) {
                    float m = 0.9f * 0.0f + v[i];
                    float s = (m > 1.0f) ? 1.0f : 0.0f;
                    mm[i] = m - s; ss[i] = s;
                }
                float* mp = g_m0T + (size_t)col * BATCH + row0;
                float* sp = g_s0T[0] + (size_t)col * BATCH + row0;
                *reinterpret_cast<float4*>(mp)     = make_float4(mm[0], mm[1], mm[2], mm[3]);
                *reinterpret_cast<float4*>(mp + 4) = make_float4(mm[4], mm[5], mm[6], mm[7]);
                *reinterpret_cast<float4*>(sp)     = make_float4(ss[0], ss[1], ss[2], ss[3]);
                *reinterpret_cast<float4*>(sp + 4) = make_float4(ss[4], ss[5], ss[6], ss[7]);
            }
        }
    }
}

// ---------------------------------------------------------------------------
// Per-warp 32x32 GEMM tile, K=2048, BK=16 double-buffered cp.async.
// micro 8x4 (TM=8 batch-rows, TN=4 feature-cols), fma.rn.f32x2.
// A: [2048][256] k-major (spike matrix, transposed). W: [2048][N].
// Epilogue: LIF; memT/spkT feature-major; optional row-major spike out (L2).
// ---------------------------------------------------------------------------
__device__ __forceinline__ void warp_gemm(
    float* wsm, uint32_t wsm_u,
    const float* __restrict__ A, const float* __restrict__ W,
    const float* __restrict__ bias,
    float* __restrict__ memT, float* __restrict__ spkT,
    float* __restrict__ outRM, int N, int bm, int bn, int lane)
{
    constexpr int KT = 2048 / 16;                  // 128 k-tiles
    // smem floats: A stages [2][16][32] at 0; B stages at 1024
    unsigned long long acc2[8][2];
    #pragma unroll
    for (int i = 0; i < 8; i++) { acc2[i][0] = 0ULL; acc2[i][1] = 0ULL; }

    const int ty = lane >> 3, tx = lane & 7;

    auto issue = [&](int st, int k0) {
        #pragma unroll
        for (int j = 0; j < 4; j++) {              // A: 16 rows x 8 chunks
            int c = lane + 32 * j;
            int kr = c >> 3, of = c & 7;
            CP_ASYNC16(wsm_u + (uint32_t)(st * 512 + kr * 32 + of * 4) * 4u,
                       A + (size_t)(k0 + kr) * BATCH + bm + of * 4);
        }
        #pragma unroll
        for (int j = 0; j < 4; j++) {              // B
            int c = lane + 32 * j;
            int kr = c >> 3, of = c & 7;
            CP_ASYNC16(wsm_u + (uint32_t)(1024 + st * 512 + kr * 32 + of * 4) * 4u,
                       W + (size_t)(k0 + kr) * N + bn + of * 4);
        }
        CP_COMMIT();
    };

    issue(0, 0);
    for (int kt = 0; kt < KT; ++kt) {
        if (kt + 1 < KT) { issue((kt + 1) & 1, (kt + 1) * 16); CP_WAIT1(); }
        else             { CP_WAIT0(); }
        __syncwarp();
        const float* sA = wsm + (kt & 1) * 512;
        const float* sB = wsm + 1024 + (kt & 1) * 512;
        #pragma unroll
        for (int k = 0; k < 16; ++k) {
            float4 a0 = *reinterpret_cast<const float4*>(sA + k * 32 + ty * 8);
            float4 a1 = *reinterpret_cast<const float4*>(sA + k * 32 + ty * 8 + 4);
            float4 bv = *reinterpret_cast<const float4*>(sB + k * 32 + tx * 4);
            unsigned long long bp0 = pk2(bv.x, bv.y), bp1 = pk2(bv.z, bv.w);
            const float a8[8] = {a0.x, a0.y, a0.z, a0.w, a1.x, a1.y, a1.z, a1.w};
            #pragma unroll
            for (int l = 0; l < 8; l++) {
                unsigned long long ad = pk2(a8[l], a8[l]);
                FMA2(acc2[l][0], ad, bp0);
                FMA2(acc2[l][1], ad, bp1);
            }
        }
        __syncwarp();                               // protect stage from next issue
    }

    // ---- LIF epilogue (identical expressions to passing kernels) ----
    const int row0 = bm + ty * 8;
    float sreg[8][4];
    #pragma unroll
    for (int p = 0; p < 2; p++) {
        #pragma unroll
        for (int q = 0; q < 2; q++) {
            const int col = bn + tx * 4 + p * 2 + q;
            const float bcol = __ldg(&bias[col]);
            float v[8];
            #pragma unroll
            for (int i = 0; i < 8; i++) {
                float c0, c1;
                upk2(c0, c1, acc2[i][p]);
                v[i] = (q ? c1 : c0) + bcol;
            }
            float* mp = memT + (size_t)col * BATCH + row0;
            float4 mlo = *reinterpret_cast<float4*>(mp);
            float4 mhi = *reinterpret_cast<float4*>(mp + 4);
            float mm[8] = {mlo.x, mlo.y, mlo.z, mlo.w, mhi.x, mhi.y, mhi.z, mhi.w};
            float ss[8];
            #pragma unroll
            for (int i = 0; i < 8; i++) {
                float m = 0.9f * mm[i] + v[i];
                float s = (m > 1.0f) ? 1.0f : 0.0f;
                mm[i] = m - s; ss[i] = s;
            }
            *reinterpret_cast<float4*>(mp)     = make_float4(mm[0], mm[1], mm[2], mm[3]);
            *reinterpret_cast<float4*>(mp + 4) = make_float4(mm[4], mm[5], mm[6], mm[7]);
            if (spkT) {
                float* sp = spkT + (size_t)col * BATCH + row0;
                *reinterpret_cast<float4*>(sp)     = make_float4(ss[0], ss[1], ss[2], ss[3]);
                *reinterpret_cast<float4*>(sp + 4) = make_float4(ss[4], ss[5], ss[6], ss[7]);
            }
            #pragma unroll
            for (int i = 0; i < 8; i++) sreg[i][p * 2 + q] = ss[i];
        }
    }
    if (outRM) {
        #pragma unroll
        for (int i = 0; i < 8; i++) {
            const int row = row0 + i;
            *reinterpret_cast<float4*>(outRM + (size_t)row * N + bn + tx * 4) =
                make_float4(sreg[i][0], sreg[i][1], sreg[i][2], sreg[i][3]);
        }
    }
}

// ---------------------------------------------------------------------------
// Step kernel: dynamic ticket queue over {L2(t) tiles, L1(t+1) tiles, lif0(t+2)}.
//   L2: 256 tiles (256x1024), L1: 512 tiles (256x2048), lif0: 32 chunks.
// ---------------------------------------------------------------------------
__global__ __launch_bounds__(128)
void step_kernel(int li, int has_l2, int l2_par, int has_l1, int l1_par,
                 int has_lif, int lif_t,
                 const float* __restrict__ b1, const float* __restrict__ b2,
                 float* __restrict__ out_t)
{
    __shared__ float sm[4 * 2048];                  // 8KB per warp
    const int warp = threadIdx.x >> 5, lane = threadIdx.x & 31;
    float* wsm = sm + warp * 2048;
    const uint32_t wsm_u = cvta_s(wsm);

    const int n_l2 = has_l2 ? 256 : 0;
    const int n_l1 = has_l1 ? 512 : 0;
    const int n_lif = has_lif ? 32 : 0;
    const int total = n_l2 + n_l1 + n_lif;

    const float* l2A = g_s1T[l2_par];
    const float* l1A = g_s0T[l1_par];
    float* l1spk = g_s1T[l1_par];

    for (;;) {
        unsigned int tk;
        if (lane == 0) tk = atomicAdd(&g_tick[li], 1u);
        tk = __shfl_sync(0xffffffffu, tk, 0);
        if (tk >= (unsigned)total) break;

        if (tk < (unsigned)n_l2) {
            const int bm = (tk >> 5) * 32, bn = (tk & 31) * 32;
            warp_gemm(wsm, wsm_u, l2A, g_wt2, b2, g_m2T, nullptr, out_t,
                      F3, bm, bn, lane);
        } else if (tk < (unsigned)(n_l2 + n_l1)) {
            const int j = tk - n_l2;
            const int bm = (j >> 6) * 32, bn = (j & 63) * 32;
            warp_gemm(wsm, wsm_u, l1A, g_wt1, b1, g_m1T, l1spk, nullptr,
                      F2, bm, bn, lane);
        } else {
            // lif0 chunk: 4096 float4 of the (F1 x BATCH) membrane plane
            const int c = tk - n_l2 - n_l1;
            const float4* c4 = reinterpret_cast<const float4*>(g_cur0T);
            float4* m4 = reinterpret_cast<float4*>(g_m0T);
            float4* s4 = reinterpret_cast<float4*>(g_s0T[lif_t & 1]);
            const int toff4 = lif_t * (BATCH / 4);
            #pragma unroll 4
            for (int j = 0; j < 128; j++) {
                int f4 = c * 4096 + j * 32 + lane;
                int n = f4 >> 6, b4 = f4 & 63;
                float4 cur = c4[(size_t)n * (M0 / 4) + toff4 + b4];
                float4 m = m4[f4];
                float4 s;
                m.x = 0.9f * m.x + cur.x; s.x = (m.x > 1.0f) ? 1.0f : 0.0f; m.x -= s.x;
                m.y = 0.9f * m.y + cur.y; s.y = (m.y > 1.0f) ? 1.0f : 0.0f; m.y -= s.y;
                m.z = 0.9f * m.z + cur.z; s.z = (m.z > 1.0f) ? 1.0f : 0.0f; m.z -= s.z;
                m.w = 0.9f * m.w + cur.w; s.w = (m.w > 1.0f) ? 1.0f : 0.0f; m.w -= s.w;
                m4[f4] = m;
                s4[f4] = s;
            }
        }
    }
}

// ---------------------------------------------------------------------------
extern "C" void kernel_launch(void* const* d_in, const int* in_sizes, int n_in,
                              void* d_out, int out_size)
{
    (void)in_sizes; (void)n_in;
    const float* x  = (const float*)d_in[0];
    const float* w0 = (const float*)d_in[1];
    const float* b0 = (const float*)d_in[2];
    const float* w1 = (const float*)d_in[3];
    const float* b1 = (const float*)d_in[4];
    const float* w2 = (const float*)d_in[5];
    const float* b2 = (const float*)d_in[6];
    float* out = (float*)d_out;

    float *wt0, *wt1, *wt2;
    cudaGetSymbolAddress((void**)&wt0, g_wt0);
    cudaGetSymbolAddress((void**)&wt1, g_wt1);
    cudaGetSymbolAddress((void**)&wt2, g_wt2);

    // prep: weight transposes + zero (membranes, ticket counters)
    {
        dim3 blk(32, 8);
        transpose_kernel<<<dim3(F0 / 32, F1 / 32), blk>>>(w0, wt0, F1, F0);
        transpose_kernel<<<dim3(F1 / 32, F2 / 32), blk>>>(w1, wt1, F2, F1);
        transpose_kernel<<<dim3(F2 / 32, F3 / 32), blk>>>(w2, wt2, F3, F2);
        zero_mems_kernel<<<512, 256>>>();
    }

    // hoisted layer-0: all currents (transposed) + lif0(t=0)
    gemm_l0<<<dim3(F1 / 128, M0 / 64), 128>>>(x, wt0, b0);

    const int GRID = 296;    // 2 CTAs per SM
    // pre-step: L1(0) + lif0(1)
    step_kernel<<<GRID, 128>>>(0, 0, 0, 1, 0, 1, 1, b1, b2, nullptr);

    // main: per step t -> L2(t) + L1(t+1) + lif0(t+2)
    for (int t = 0; t < T_STEPS - 1; ++t) {
        const int has_lif = (t + 2) < T_STEPS ? 1 : 0;
        step_kernel<<<GRID, 128>>>(1 + t, 1, t & 1, 1, (t + 1) & 1,
                                   has_lif, t + 2, b1, b2,
                                   out + (size_t)t * BATCH * F3);
    }
    // final: L2(24) only
    step_kernel<<<GRID, 128>>>(25, 1, (T_STEPS - 1) & 1, 0, 0, 0, 0,
                               b1, b2, out + (size_t)(T_STEPS - 1) * BATCH * F3);

    const long long mem_off = (long long)T_STEPS * BATCH * F3;
    if ((long long)out_size >= mem_off + (long long)BATCH * F3) {
        copy_final_mem_kernel<<<(BATCH * F3 + 255) / 256, 256>>>(out + mem_off);
    }
}

// round 13
// speedup vs baseline: 1.6025x; 1.0578x over previous
#include <cuda_runtime.h>
#include <cstdint>

// ---------------------------------------------------------------------------
// SNN forward — fp32 bit-exact-chain, v5.
//   Identical per-output fp32 accumulation chain (ascending k) to R9-R12.
//   * layer-1: dense 32x32 warp tiles (micro 8x4, fma.rn.f32x2), 512 tiles
//     per step  ->  fits in one 592-SMSP quantum (was 768 -> 2 quanta).
//   * layer-2: SPARSE. Spikes are exactly 0/1, so skipping zeros and doing
//     add.rn.f32x2 of W2 rows for active k (ascending) is bit-identical to
//     the dense FMA chain. s1 density ~5% -> ~10us, overlapped on the queue.
//   * layer-0 hoisted GEMM + per-step lif0 chunks unchanged from R12.
// Output: [0, 25*256*1024) layer-2 spike record; then (256*1024) final mem2.
// ---------------------------------------------------------------------------

constexpr int T_STEPS = 25;
constexpr int BATCH   = 256;
constexpr int F0 = 1024, F1 = 2048, F2 = 2048, F3 = 1024;
constexpr int M0 = T_STEPS * BATCH;              // 6400

__device__ float g_wt0[F0 * F1];                 // W0^T [k][n]
__device__ float g_wt1[F1 * F2];                 // W1^T [k][n]
__device__ float g_wt2[F2 * F3];                 // W2^T [k][n]
__device__ float g_cur0T[F1 * M0];               // layer-0 currents, [n][t*B+b]
__device__ float g_m0T[F1 * BATCH];              // layer-0 membranes, feature-major
__device__ float g_m1T[F2 * BATCH];              // layer-1 membranes, feature-major
__device__ float g_m2RM[BATCH * F3];             // layer-2 membranes, row-major
__device__ float g_s0T[2][F1 * BATCH];           // layer-0 spikes, k-major, dbl-buf
__device__ float g_s1RM[2][BATCH * F2];          // layer-1 spikes, row-major, dbl-buf
__device__ unsigned int g_tick[32];              // per-launch ticket counters

// ----- packed f32x2 helpers (independent correctly-rounded fp32 lanes) --------
__device__ __forceinline__ unsigned long long pk2(float x, float y) {
    unsigned long long r;
    asm("mov.b64 %0, {%1, %2};" : "=l"(r) : "f"(x), "f"(y));
    return r;
}
__device__ __forceinline__ void upk2(float& x, float& y, unsigned long long v) {
    asm("mov.b64 {%0, %1}, %2;" : "=f"(x), "=f"(y) : "l"(v));
}
#define FMA2(acc, a, b) \
    asm("fma.rn.f32x2 %0, %1, %2, %0;" : "+l"(acc) : "l"(a), "l"(b))
#define ADD2(acc, v) \
    asm("add.rn.f32x2 %0, %0, %1;" : "+l"(acc) : "l"(v))

#define CP_ASYNC16(dst, src) \
    asm volatile("cp.async.cg.shared.global [%0], [%1], 16;\n" :: "r"(dst), "l"(src))
#define CP_COMMIT() asm volatile("cp.async.commit_group;\n")
#define CP_WAIT1()  asm volatile("cp.async.wait_group 1;\n")
#define CP_WAIT0()  asm volatile("cp.async.wait_group 0;\n")

__device__ __forceinline__ uint32_t cvta_s(const void* p) {
    return (uint32_t)__cvta_generic_to_shared(p);
}

// ----- prep kernels -------------------------------------------------------------
__global__ void zero_mems_kernel() {
    int idx = blockIdx.x * blockDim.x + threadIdx.x;
    int stride = gridDim.x * blockDim.x;
    for (int i = idx; i < BATCH * F2; i += stride) g_m1T[i] = 0.0f;
    for (int i = idx; i < BATCH * F3; i += stride) g_m2RM[i] = 0.0f;
    if (idx < 32) g_tick[idx] = 0u;
}

__global__ void transpose_kernel(const float* __restrict__ src,
                                 float* __restrict__ dst, int R, int C) {
    __shared__ float tile[32][33];
    int c0 = blockIdx.x * 32, r0 = blockIdx.y * 32;
    int tx = threadIdx.x, ty = threadIdx.y;          // 32 x 8
    #pragma unroll
    for (int j = 0; j < 32; j += 8)
        tile[ty + j][tx] = src[(size_t)(r0 + ty + j) * C + c0 + tx];
    __syncthreads();
    #pragma unroll
    for (int j = 0; j < 32; j += 8)
        dst[(size_t)(c0 + ty + j) * R + r0 + tx] = tile[tx][ty + j];
}

__global__ void copy_final_mem_kernel(float* __restrict__ dst) {
    int i = blockIdx.x * blockDim.x + threadIdx.x;
    if (i < BATCH * F3) dst[i] = g_m2RM[i];
}

// ---------------------------------------------------------------------------
// Hoisted layer-0 GEMM (M=6400): BM=64 x BN=128 x BK=32, micro 8x8, 128 thr.
// Writes currents TRANSPOSED (cur0T[n][m]); fused lif0 for t=0 rows.
// (unchanged from passing R12)
// ---------------------------------------------------------------------------
__global__ __launch_bounds__(128)
void gemm_l0(const float* __restrict__ A,
             const float* __restrict__ WT,
             const float* __restrict__ bias)
{
    constexpr int BM = 64, BN = 128, BK = 32, K = F0, N = F1;
    __shared__ float As[2][BK][BM + 4];
    __shared__ float Bs[2][BK][BN + 4];

    const int tid = threadIdx.x;
    const int tx = tid & 15, ty = tid >> 4;
    const int bn = blockIdx.x * BN, bm = blockIdx.y * BM;
    const int am = tid & 15, akc = tid >> 4;
    const int bnc = tid & 31, bkr = tid >> 5;

    unsigned long long acc2[8][4];
    #pragma unroll
    for (int i = 0; i < 8; i++)
        #pragma unroll
        for (int p = 0; p < 4; p++) acc2[i][p] = 0ULL;

    const int ktiles = K / BK;
    float4 pa[4];

    #pragma unroll
    for (int i = 0; i < 8; i++)
        CP_ASYNC16(cvta_s(&Bs[0][bkr + 4 * i][bnc * 4]),
                   WT + (size_t)(bkr + 4 * i) * N + bn + bnc * 4);
    CP_COMMIT();
    #pragma unroll
    for (int i = 0; i < 4; i++)
        pa[i] = *reinterpret_cast<const float4*>(A + (size_t)(bm + am + 16 * i) * K + akc * 4);
    #pragma unroll
    for (int i = 0; i < 4; i++) {
        As[0][akc * 4 + 0][am + 16 * i] = pa[i].x;
        As[0][akc * 4 + 1][am + 16 * i] = pa[i].y;
        As[0][akc * 4 + 2][am + 16 * i] = pa[i].z;
        As[0][akc * 4 + 3][am + 16 * i] = pa[i].w;
    }
    CP_WAIT0();
    __syncthreads();

    for (int kt = 0; kt < ktiles; ++kt) {
        const int buf = kt & 1;
        if (kt + 1 < ktiles) {
            const int k0 = (kt + 1) * BK;
            #pragma unroll
            for (int i = 0; i < 8; i++)
                CP_ASYNC16(cvta_s(&Bs[buf ^ 1][bkr + 4 * i][bnc * 4]),
                           WT + (size_t)(k0 + bkr + 4 * i) * N + bn + bnc * 4);
            CP_COMMIT();
            #pragma unroll
            for (int i = 0; i < 4; i++)
                pa[i] = *reinterpret_cast<const float4*>(
                    A + (size_t)(bm + am + 16 * i) * K + k0 + akc * 4);
        }
        #pragma unroll
        for (int k = 0; k < BK; ++k) {
            float4 av0 = *reinterpret_cast<const float4*>(&As[buf][k][ty * 8]);
            float4 av1 = *reinterpret_cast<const float4*>(&As[buf][k][ty * 8 + 4]);
            float4 bv0 = *reinterpret_cast<const float4*>(&Bs[buf][k][tx * 8]);
            float4 bv1 = *reinterpret_cast<const float4*>(&Bs[buf][k][tx * 8 + 4]);
            unsigned long long bp[4] = {pk2(bv0.x, bv0.y), pk2(bv0.z, bv0.w),
                                        pk2(bv1.x, bv1.y), pk2(bv1.z, bv1.w)};
            const float a8[8] = {av0.x, av0.y, av0.z, av0.w, av1.x, av1.y, av1.z, av1.w};
            #pragma unroll
            for (int l = 0; l < 8; l++) {
                unsigned long long ad = pk2(a8[l], a8[l]);
                #pragma unroll
                for (int p = 0; p < 4; p++) FMA2(acc2[l][p], ad, bp[p]);
            }
        }
        if (kt + 1 < ktiles) {
            const int nb = buf ^ 1;
            #pragma unroll
            for (int i = 0; i < 4; i++) {
                As[nb][akc * 4 + 0][am + 16 * i] = pa[i].x;
                As[nb][akc * 4 + 1][am + 16 * i] = pa[i].y;
                As[nb][akc * 4 + 2][am + 16 * i] = pa[i].z;
                As[nb][akc * 4 + 3][am + 16 * i] = pa[i].w;
            }
        }
        CP_WAIT0();
        __syncthreads();
    }

    const int row0 = bm + ty * 8;
    #pragma unroll
    for (int p = 0; p < 4; p++) {
        #pragma unroll
        for (int q = 0; q < 2; q++) {
            const int col = bn + tx * 8 + p * 2 + q;
            const float bcol = __ldg(&bias[col]);
            float v[8];
            #pragma unroll
            for (int i = 0; i < 8; i++) {
                float c0, c1;
                upk2(c0, c1, acc2[i][p]);
                v[i] = (q ? c1 : c0) + bcol;
            }
            float* cp = g_cur0T + (size_t)col * M0 + row0;
            *reinterpret_cast<float4*>(cp)     = make_float4(v[0], v[1], v[2], v[3]);
            *reinterpret_cast<float4*>(cp + 4) = make_float4(v[4], v[5], v[6], v[7]);
            if (bm < BATCH) {
                float mm[8], ss[8];
                #pragma unroll
                for (int i = 0; i < 8; i++) {
                    float m = 0.9f * 0.0f + v[i];
                    float s = (m > 1.0f) ? 1.0f : 0.0f;
                    mm[i] = m - s; ss[i] = s;
                }
                float* mp = g_m0T + (size_t)col * BATCH + row0;
                float* sp = g_s0T[0] + (size_t)col * BATCH + row0;
                *reinterpret_cast<float4*>(mp)     = make_float4(mm[0], mm[1], mm[2], mm[3]);
                *reinterpret_cast<float4*>(mp + 4) = make_float4(mm[4], mm[5], mm[6], mm[7]);
                *reinterpret_cast<float4*>(sp)     = make_float4(ss[0], ss[1], ss[2], ss[3]);
                *reinterpret_cast<float4*>(sp + 4) = make_float4(ss[4], ss[5], ss[6], ss[7]);
            }
        }
    }
}

// ---------------------------------------------------------------------------
// Dense per-warp 32x32 GEMM tile for layer 1 (K=2048, BK=16, cp.async dblbuf).
// A: s0T [2048][256] k-major. W: wt1 [2048][2048].
// Epilogue: LIF -> m1T (feature-major) + s1 row-major (for the sparse L2 scan).
// ---------------------------------------------------------------------------
__device__ __forceinline__ void warp_gemm_l1(
    float* wsm, uint32_t wsm_u,
    const float* __restrict__ A, const float* __restrict__ W,
    const float* __restrict__ bias,
    float* __restrict__ memT, float* __restrict__ s1rm,
    int bm, int bn, int lane)
{
    constexpr int KT = 2048 / 16;
    constexpr int N = F2;
    unsigned long long acc2[8][2];
    #pragma unroll
    for (int i = 0; i < 8; i++) { acc2[i][0] = 0ULL; acc2[i][1] = 0ULL; }

    const int ty = lane >> 3, tx = lane & 7;

    auto issue = [&](int st, int k0) {
        #pragma unroll
        for (int j = 0; j < 4; j++) {
            int c = lane + 32 * j;
            int kr = c >> 3, of = c & 7;
            CP_ASYNC16(wsm_u + (uint32_t)(st * 512 + kr * 32 + of * 4) * 4u,
                       A + (size_t)(k0 + kr) * BATCH + bm + of * 4);
        }
        #pragma unroll
        for (int j = 0; j < 4; j++) {
            int c = lane + 32 * j;
            int kr = c >> 3, of = c & 7;
            CP_ASYNC16(wsm_u + (uint32_t)(1024 + st * 512 + kr * 32 + of * 4) * 4u,
                       W + (size_t)(k0 + kr) * N + bn + of * 4);
        }
        CP_COMMIT();
    };

    issue(0, 0);
    for (int kt = 0; kt < KT; ++kt) {
        if (kt + 1 < KT) { issue((kt + 1) & 1, (kt + 1) * 16); CP_WAIT1(); }
        else             { CP_WAIT0(); }
        __syncwarp();
        const float* sA = wsm + (kt & 1) * 512;
        const float* sB = wsm + 1024 + (kt & 1) * 512;
        #pragma unroll
        for (int k = 0; k < 16; ++k) {
            float4 a0 = *reinterpret_cast<const float4*>(sA + k * 32 + ty * 8);
            float4 a1 = *reinterpret_cast<const float4*>(sA + k * 32 + ty * 8 + 4);
            float4 bv = *reinterpret_cast<const float4*>(sB + k * 32 + tx * 4);
            unsigned long long bp0 = pk2(bv.x, bv.y), bp1 = pk2(bv.z, bv.w);
            const float a8[8] = {a0.x, a0.y, a0.z, a0.w, a1.x, a1.y, a1.z, a1.w};
            #pragma unroll
            for (int l = 0; l < 8; l++) {
                unsigned long long ad = pk2(a8[l], a8[l]);
                FMA2(acc2[l][0], ad, bp0);
                FMA2(acc2[l][1], ad, bp1);
            }
        }
        __syncwarp();
    }

    // LIF epilogue (identical expressions to passing kernels)
    const int row0 = bm + ty * 8;
    float sreg[8][4];
    #pragma unroll
    for (int p = 0; p < 2; p++) {
        #pragma unroll
        for (int q = 0; q < 2; q++) {
            const int col = bn + tx * 4 + p * 2 + q;
            const float bcol = __ldg(&bias[col]);
            float v[8];
            #pragma unroll
            for (int i = 0; i < 8; i++) {
                float c0, c1;
                upk2(c0, c1, acc2[i][p]);
                v[i] = (q ? c1 : c0) + bcol;
            }
            float* mp = memT + (size_t)col * BATCH + row0;
            float4 mlo = *reinterpret_cast<float4*>(mp);
            float4 mhi = *reinterpret_cast<float4*>(mp + 4);
            float mm[8] = {mlo.x, mlo.y, mlo.z, mlo.w, mhi.x, mhi.y, mhi.z, mhi.w};
            float ss[8];
            #pragma unroll
            for (int i = 0; i < 8; i++) {
                float m = 0.9f * mm[i] + v[i];
                float s = (m > 1.0f) ? 1.0f : 0.0f;
                mm[i] = m - s; ss[i] = s;
            }
            *reinterpret_cast<float4*>(mp)     = make_float4(mm[0], mm[1], mm[2], mm[3]);
            *reinterpret_cast<float4*>(mp + 4) = make_float4(mm[4], mm[5], mm[6], mm[7]);
            #pragma unroll
            for (int i = 0; i < 8; i++) sreg[i][p * 2 + q] = ss[i];
        }
    }
    #pragma unroll
    for (int i = 0; i < 8; i++) {
        const int row = row0 + i;
        *reinterpret_cast<float4*>(s1rm + (size_t)row * N + bn + tx * 4) =
            make_float4(sreg[i][0], sreg[i][1], sreg[i][2], sreg[i][3]);
    }
}

// ---------------------------------------------------------------------------
// SPARSE layer-2 task: one warp = (batch row b, 512-feature slice n0).
// Chain: for k ascending, if s1[b][k]==1 then acc[n] += W2T[k][n]  (add.rn
// is bit-identical to the dense fma chain because s is exactly 0/1).
// Then cur = acc + bias; LIF on m2RM; spikes -> out (row-major).
// ---------------------------------------------------------------------------
__device__ __forceinline__ void sparse_l2(
    const float* __restrict__ s1b,          // s1RM + b*F2
    const float* __restrict__ W2T,
    const float* __restrict__ bias,
    float* __restrict__ m2b,                // m2RM + b*F3
    float* __restrict__ outb,               // out_t + b*F3
    int n0, int lane)
{
    unsigned long long acc[4][2];
    #pragma unroll
    for (int c = 0; c < 4; c++) { acc[c][0] = 0ULL; acc[c][1] = 0ULL; }

    for (int base = 0; base < F2; base += 128) {
        const float4 sv = *reinterpret_cast<const float4*>(s1b + base + lane * 4);
        unsigned bl0 = __ballot_sync(0xffffffffu, sv.x != 0.0f);
        unsigned bl1 = __ballot_sync(0xffffffffu, sv.y != 0.0f);
        unsigned bl2 = __ballot_sync(0xffffffffu, sv.z != 0.0f);
        unsigned bl3 = __ballot_sync(0xffffffffu, sv.w != 0.0f);
        unsigned any = bl0 | bl1 | bl2 | bl3;
        while (any) {
            const int L = __ffs(any) - 1;
            any &= any - 1;
            const int kb = base + L * 4;
            #pragma unroll
            for (int j = 0; j < 4; j++) {
                const unsigned blj = (j == 0) ? bl0 : (j == 1) ? bl1 : (j == 2) ? bl2 : bl3;
                if ((blj >> L) & 1u) {
                    const float* wr = W2T + (size_t)(kb + j) * F3 + n0;
                    #pragma unroll
                    for (int c = 0; c < 4; c++) {
                        float4 w = *reinterpret_cast<const float4*>(wr + c * 128 + lane * 4);
                        ADD2(acc[c][0], pk2(w.x, w.y));
                        ADD2(acc[c][1], pk2(w.z, w.w));
                    }
                }
            }
        }
    }

    // LIF epilogue (identical expressions)
    #pragma unroll
    for (int c = 0; c < 4; c++) {
        const int n = n0 + c * 128 + lane * 4;
        float a0, a1, a2, a3;
        upk2(a0, a1, acc[c][0]);
        upk2(a2, a3, acc[c][1]);
        float4 bv = *reinterpret_cast<const float4*>(bias + n);
        float4 mv = *reinterpret_cast<const float4*>(m2b + n);
        float cur0 = a0 + bv.x, cur1 = a1 + bv.y, cur2 = a2 + bv.z, cur3 = a3 + bv.w;
        float m0 = 0.9f * mv.x + cur0, s0 = (m0 > 1.0f) ? 1.0f : 0.0f;
        float m1 = 0.9f * mv.y + cur1, s1 = (m1 > 1.0f) ? 1.0f : 0.0f;
        float m2 = 0.9f * mv.z + cur2, s2 = (m2 > 1.0f) ? 1.0f : 0.0f;
        float m3 = 0.9f * mv.w + cur3, s3 = (m3 > 1.0f) ? 1.0f : 0.0f;
        *reinterpret_cast<float4*>(m2b + n) =
            make_float4(m0 - s0, m1 - s1, m2 - s2, m3 - s3);
        *reinterpret_cast<float4*>(outb + n) = make_float4(s0, s1, s2, s3);
    }
}

// ---------------------------------------------------------------------------
// Step kernel, dynamic ticket queue:
//   [0, nL1)          : dense layer-1 tiles (512 = 8 m x 64 n)
//   [nL1, +nSP)       : sparse layer-2 tasks (512 = 256 b x 2 slices)
//   [.., +nLIF)       : lif0 chunks (32)
// ---------------------------------------------------------------------------
__global__ __launch_bounds__(128)
void step_kernel(int li,
                 int has_l1, int l1_par,      // L1(t+1): reads s0T[l1_par], writes s1RM[l1_par]
                 int has_sp, int sp_par,      // L2(t):   reads s1RM[sp_par]
                 int has_lif, int lif_t,      // lif0(t+2) -> s0T[lif_t&1]
                 const float* __restrict__ b1, const float* __restrict__ b2,
                 float* __restrict__ out_t)
{
    __shared__ float sm[4 * 2048];
    const int warp = threadIdx.x >> 5, lane = threadIdx.x & 31;
    float* wsm = sm + warp * 2048;
    const uint32_t wsm_u = cvta_s(wsm);

    const int nL1 = has_l1 ? 512 : 0;
    const int nSP = has_sp ? 512 : 0;
    const int nLIF = has_lif ? 32 : 0;
    const int total = nL1 + nSP + nLIF;

    const float* l1A = g_s0T[l1_par];
    float* l1spk = g_s1RM[l1_par];
    const float* spS = g_s1RM[sp_par];

    for (;;) {
        unsigned int tk;
        if (lane == 0) tk = atomicAdd(&g_tick[li], 1u);
        tk = __shfl_sync(0xffffffffu, tk, 0);
        if (tk >= (unsigned)total) break;

        if (tk < (unsigned)nL1) {
            const int bm = (tk >> 6) * 32, bn = (int)(tk & 63) * 32;
            warp_gemm_l1(wsm, wsm_u, l1A, g_wt1, b1, g_m1T, l1spk, bm, bn, lane);
        } else if (tk < (unsigned)(nL1 + nSP)) {
            const int j = tk - nL1;
            const int b = j >> 1, n0 = (j & 1) * 512;
            sparse_l2(spS + (size_t)b * F2, g_wt2, b2,
                      g_m2RM + (size_t)b * F3, out_t + (size_t)b * F3, n0, lane);
        } else {
            const int c = tk - nL1 - nSP;
            const float4* c4 = reinterpret_cast<const float4*>(g_cur0T);
            float4* m4 = reinterpret_cast<float4*>(g_m0T);
            float4* s4 = reinterpret_cast<float4*>(g_s0T[lif_t & 1]);
            const int toff4 = lif_t * (BATCH / 4);
            #pragma unroll 4
            for (int j = 0; j < 128; j++) {
                int f4 = c * 4096 + j * 32 + lane;
                int n = f4 >> 6, b4 = f4 & 63;
                float4 cur = c4[(size_t)n * (M0 / 4) + toff4 + b4];
                float4 m = m4[f4];
                float4 s;
                m.x = 0.9f * m.x + cur.x; s.x = (m.x > 1.0f) ? 1.0f : 0.0f; m.x -= s.x;
                m.y = 0.9f * m.y + cur.y; s.y = (m.y > 1.0f) ? 1.0f : 0.0f; m.y -= s.y;
                m.z = 0.9f * m.z + cur.z; s.z = (m.z > 1.0f) ? 1.0f : 0.0f; m.z -= s.z;
                m.w = 0.9f * m.w + cur.w; s.w = (m.w > 1.0f) ? 1.0f : 0.0f; m.w -= s.w;
                m4[f4] = m;
                s4[f4] = s;
            }
        }
    }
}

// ---------------------------------------------------------------------------
extern "C" void kernel_launch(void* const* d_in, const int* in_sizes, int n_in,
                              void* d_out, int out_size)
{
    (void)in_sizes; (void)n_in;
    const float* x  = (const float*)d_in[0];
    const float* w0 = (const float*)d_in[1];
    const float* b0 = (const float*)d_in[2];
    const float* w1 = (const float*)d_in[3];
    const float* b1 = (const float*)d_in[4];
    const float* w2 = (const float*)d_in[5];
    const float* b2 = (const float*)d_in[6];
    float* out = (float*)d_out;

    float *wt0, *wt1, *wt2;
    cudaGetSymbolAddress((void**)&wt0, g_wt0);
    cudaGetSymbolAddress((void**)&wt1, g_wt1);
    cudaGetSymbolAddress((void**)&wt2, g_wt2);

    {
        dim3 blk(32, 8);
        transpose_kernel<<<dim3(F0 / 32, F1 / 32), blk>>>(w0, wt0, F1, F0);
        transpose_kernel<<<dim3(F1 / 32, F2 / 32), blk>>>(w1, wt1, F2, F1);
        transpose_kernel<<<dim3(F2 / 32, F3 / 32), blk>>>(w2, wt2, F3, F2);
        zero_mems_kernel<<<512, 256>>>();
    }

    // hoisted layer-0: all currents (transposed) + lif0(t=0)
    gemm_l0<<<dim3(F1 / 128, M0 / 64), 128>>>(x, wt0, b0);

    const int GRID = 296;
    // pre-step: L1(0) + lif0(1)
    step_kernel<<<GRID, 128>>>(0, 1, 0, 0, 0, 1, 1, b1, b2, out);

    // main: per step t -> sparse L2(t) + dense L1(t+1) + lif0(t+2)
    for (int t = 0; t < T_STEPS - 1; ++t) {
        const int has_lif = (t + 2) < T_STEPS ? 1 : 0;
        step_kernel<<<GRID, 128>>>(1 + t,
                                   1, (t + 1) & 1,
                                   1, t & 1,
                                   has_lif, t + 2,
                                   b1, b2, out + (size_t)t * BATCH * F3);
    }
    // final: sparse L2(24) only
    step_kernel<<<GRID, 128>>>(25, 0, 0, 1, (T_STEPS - 1) & 1, 0, 0,
                               b1, b2, out + (size_t)(T_STEPS - 1) * BATCH * F3);

    const long long mem_off = (long long)T_STEPS * BATCH * F3;
    if ((long long)out_size >= mem_off + (long long)BATCH * F3) {
        copy_final_mem_kernel<<<(BATCH * F3 + 255) / 256, 256>>>(out + mem_off);
    }
}